// round 4
// baseline (speedup 1.0000x reference)
#include <cuda_runtime.h>

#define NN 20000
#define EE 320000
#define GG 256
#define N2 (2 * NN)
#define E2 (2 * EE)

// -------- scratch (static device globals; no runtime allocation) --------
__device__ float g_bufA[(N2 + 256) * 160];   // agg outputs / GEMM A
__device__ float g_bufP[(N2 + 256) * 80];    // prescaled h (layer-2 input)
__device__ float g_bufQ[(N2 + 256) * 160];   // prescaled h (layer-3 input)
__device__ float g_bufB[(N2 + 256) * 312];   // layer-3 output (pool input)
__device__ int   g_work[2 * N2];             // cnt | fill
__device__ int   g_offs[N2 + 1];
__device__ int   g_csr[E2];
__device__ float g_dinv[N2];
__device__ float g_pool[2 * GG * 312];
__device__ float g_xc[GG * 512];
__device__ float g_t0[2 * GG * 2048];
__device__ float g_t1[2 * GG * 2048];
__device__ float g_part[8 * GG * 1024];

// -------- f32x2 packed FMA helper --------
__device__ __forceinline__ void fma2(unsigned long long& d, unsigned long long a,
                                     unsigned long long b) {
    asm("fma.rn.f32x2 %0, %1, %2, %0;" : "+l"(d) : "l"(a), "l"(b));
}
union U2 { unsigned long long u; float2 f; };

// -------- CSR build over combined graph --------
__global__ void k_count2(const int* __restrict__ ei1, const int* __restrict__ ei2,
                         int* __restrict__ cnt) {
    int e = blockIdx.x * blockDim.x + threadIdx.x;
    if (e < EE) atomicAdd(&cnt[ei1[EE + e]], 1);
    else if (e < E2) atomicAdd(&cnt[ei2[EE + (e - EE)] + NN], 1);
}

__global__ void k_scan_dinv(const int* __restrict__ cnt, int* __restrict__ offs,
                            float* __restrict__ dinv) {
    const int T = 1024;
    const int IPT = (N2 + T - 1) / T;
    __shared__ int s[T];
    int tid = threadIdx.x;
    int base = tid * IPT;
    int local = 0;
    #pragma unroll
    for (int i = 0; i < IPT; i++) {
        int idx = base + i;
        if (idx < N2) {
            int c = cnt[idx];
            local += c;
            dinv[idx] = rsqrtf((float)(c + 1));
        }
    }
    s[tid] = local;
    __syncthreads();
    for (int off = 1; off < T; off <<= 1) {
        int v = 0;
        if (tid >= off) v = s[tid - off];
        __syncthreads();
        if (tid >= off) s[tid] += v;
        __syncthreads();
    }
    int run = (tid == 0) ? 0 : s[tid - 1];
    #pragma unroll
    for (int i = 0; i < IPT; i++) {
        int idx = base + i;
        if (idx < N2) { offs[idx] = run; run += cnt[idx]; }
    }
    if (tid == 0) offs[N2] = s[T - 1];
}

__global__ void k_fill2(const int* __restrict__ ei1, const int* __restrict__ ei2,
                        const int* __restrict__ offs, int* __restrict__ fill,
                        int* __restrict__ csr) {
    int e = blockIdx.x * blockDim.x + threadIdx.x;
    int s, d;
    if (e < EE) { s = ei1[e]; d = ei1[EE + e]; }
    else if (e < E2) { s = ei2[e - EE] + NN; d = ei2[EE + (e - EE)] + NN; }
    else return;
    int p = atomicAdd(&fill[d], 1);
    csr[offs[d] + p] = s;
}

// -------- layer-1 aggregation: raw x1/x2 inputs, scales by dinv inside --------
__global__ void k_agg_l1(const float* __restrict__ h0, const float* __restrict__ h1,
                         const int* __restrict__ offs, const int* __restrict__ csr,
                         const float* __restrict__ dinv, float* __restrict__ out) {
    int warp = (blockIdx.x * blockDim.x + threadIdx.x) >> 5;
    int lane = threadIdx.x & 31;
    if (warp >= N2) return;
    int n = warp;
    const float* hn = (n < NN) ? h0 + (size_t)n * 78 : h1 + (size_t)(n - NN) * 78;
    float din = dinv[n];
    float acc[3];
    #pragma unroll
    for (int r = 0; r < 3; r++) {
        int f = lane + 32 * r;
        acc[r] = (f < 78) ? din * hn[f] : 0.f;
    }
    int e0 = offs[n], e1 = offs[n + 1];
    for (int e = e0; e < e1; e++) {
        int s = csr[e];
        const float* hs = (s < NN) ? h0 + (size_t)s * 78 : h1 + (size_t)(s - NN) * 78;
        float ds = dinv[s];
        #pragma unroll
        for (int r = 0; r < 3; r++) {
            int f = lane + 32 * r;
            if (f < 78) acc[r] += ds * hs[f];
        }
    }
    #pragma unroll
    for (int r = 0; r < 3; r++) {
        int f = lane + 32 * r;
        if (f < 78) out[(size_t)n * 80 + f] = din * acc[r];
    }
}

// -------- prescaled scalar aggregation (layer-2, DIM=78, ld 80) --------
__global__ void k_agg_pre(const float* __restrict__ hp, const int* __restrict__ offs,
                          const int* __restrict__ csr, const float* __restrict__ dinv,
                          float* __restrict__ out) {
    int warp = (blockIdx.x * blockDim.x + threadIdx.x) >> 5;
    int lane = threadIdx.x & 31;
    if (warp >= N2) return;
    int n = warp;
    float acc[3];
    #pragma unroll
    for (int r = 0; r < 3; r++) {
        int f = lane + 32 * r;
        acc[r] = (f < 78) ? hp[(size_t)n * 80 + f] : 0.f;   // hp already dinv-scaled
    }
    int e0 = offs[n], e1 = offs[n + 1];
    int e = e0;
    for (; e + 2 <= e1; e += 2) {
        int s0 = csr[e], s1 = csr[e + 1];
        const float* p0 = hp + (size_t)s0 * 80;
        const float* p1 = hp + (size_t)s1 * 80;
        #pragma unroll
        for (int r = 0; r < 3; r++) {
            int f = lane + 32 * r;
            if (f < 78) acc[r] += p0[f] + p1[f];
        }
    }
    if (e < e1) {
        const float* p0 = hp + (size_t)csr[e] * 80;
        #pragma unroll
        for (int r = 0; r < 3; r++) {
            int f = lane + 32 * r;
            if (f < 78) acc[r] += p0[f];
        }
    }
    float din = dinv[n];
    #pragma unroll
    for (int r = 0; r < 3; r++) {
        int f = lane + 32 * r;
        if (f < 78) out[(size_t)n * 80 + f] = din * acc[r];
    }
}

// -------- prescaled float2 aggregation (layer-3, DIM=156, ld 160) --------
__global__ void k_agg_pre2(const float* __restrict__ hp, const int* __restrict__ offs,
                           const int* __restrict__ csr, const float* __restrict__ dinv,
                           float* __restrict__ out) {
    int warp = (blockIdx.x * blockDim.x + threadIdx.x) >> 5;
    int lane = threadIdx.x & 31;
    if (warp >= N2) return;
    int n = warp;
    const float2* pn = (const float2*)(hp + (size_t)n * 160);
    float2 acc[3];
    #pragma unroll
    for (int r = 0; r < 3; r++) {
        int idx = lane + 32 * r;            // float2 index, valid < 78
        acc[r] = (idx < 78) ? pn[idx] : make_float2(0.f, 0.f);
    }
    int e0 = offs[n], e1 = offs[n + 1];
    int e = e0;
    for (; e + 2 <= e1; e += 2) {
        int s0 = csr[e], s1 = csr[e + 1];
        const float2* p0 = (const float2*)(hp + (size_t)s0 * 160);
        const float2* p1 = (const float2*)(hp + (size_t)s1 * 160);
        #pragma unroll
        for (int r = 0; r < 3; r++) {
            int idx = lane + 32 * r;
            if (idx < 78) {
                float2 v0 = p0[idx], v1 = p1[idx];
                acc[r].x += v0.x + v1.x;
                acc[r].y += v0.y + v1.y;
            }
        }
    }
    if (e < e1) {
        const float2* p0 = (const float2*)(hp + (size_t)csr[e] * 160);
        #pragma unroll
        for (int r = 0; r < 3; r++) {
            int idx = lane + 32 * r;
            if (idx < 78) {
                float2 v0 = p0[idx];
                acc[r].x += v0.x;
                acc[r].y += v0.y;
            }
        }
    }
    float din = dinv[n];
    float2* po = (float2*)(out + (size_t)n * 160);
    #pragma unroll
    for (int r = 0; r < 3; r++) {
        int idx = lane + 32 * r;
        if (idx < 78) po[idx] = make_float2(din * acc[r].x, din * acc[r].y);
    }
}

// -------- global max pool over combined nodes -> pool[2*G, 312] --------
__global__ void k_pool(const float* __restrict__ h,
                       const int* __restrict__ bat1, const int* __restrict__ bat2,
                       float* __restrict__ pool) {
    const int CH = 32;
    const int NCH = N2 / CH;
    int idx = blockIdx.x * blockDim.x + threadIdx.x;
    if (idx >= NCH * 312) return;
    int f = idx % 312;
    int c = idx / 312;
    int n0 = c * CH;
    int n1 = n0 + CH;
    int curb = (n0 < NN) ? bat1[n0] : GG + bat2[n0 - NN];
    float m = 0.f;
    for (int n = n0; n < n1; n++) {
        int b = (n < NN) ? bat1[n] : GG + bat2[n - NN];
        if (b != curb) {
            atomicMax((int*)&pool[curb * 312 + f], __float_as_int(m));
            curb = b;
            m = 0.f;
        }
        m = fmaxf(m, h[(size_t)n * 312 + f]);
    }
    atomicMax((int*)&pool[curb * 312 + f], __float_as_int(m));
}

// -------- scatter branch-MLP output [2G,128] -> xc[G,512] --------
__global__ void k_scatter(const float* __restrict__ t, float* __restrict__ xc) {
    int i = blockIdx.x * blockDim.x + threadIdx.x;
    if (i >= 2 * GG * 128) return;
    int r = i >> 7, j = i & 127;
    int br = r >> 8;
    int g = r & 255;
    xc[g * 512 + br * 128 + j] = t[i];
}

// -------- L2 row normalize --------
__global__ void k_norm(const float* __restrict__ cell, float* __restrict__ out) {
    int g = blockIdx.x;
    __shared__ float s[256];
    float ss = 0.f;
    for (int j = threadIdx.x; j < 954; j += 256) {
        float v = cell[g * 954 + j];
        ss += v * v;
    }
    s[threadIdx.x] = ss;
    __syncthreads();
    for (int o = 128; o > 0; o >>= 1) {
        if (threadIdx.x < o) s[threadIdx.x] += s[threadIdx.x + o];
        __syncthreads();
    }
    float inv = 1.f / fmaxf(sqrtf(s[0]), 1e-12f);
    for (int j = threadIdx.x; j < 954; j += 256)
        out[g * 954 + j] = cell[g * 954 + j] * inv;
}

// -------- node SGEMM: 128x128 tiles, BK=8, double-buffered, f32x2 FMA (8x8/thread).
// A reads unguarded float4 (pad garbage harmless: B rows k>=K are zeroed).
// PRESCALE: epilogue multiplies rows by dinv[m] (for feeding the next aggregation).
template <bool RELU, bool PRESCALE>
__global__ __launch_bounds__(256)
void k_gemm128(const float* __restrict__ A, int lda,
               const float* __restrict__ B,
               const float* __restrict__ bias,
               const float* __restrict__ dinv,
               float* __restrict__ C, int ldc,
               int M, int N, int K) {
    const int BK = 8;
    __shared__ float As[2][BK][128];
    __shared__ float Bs2[2][BK][256];   // duplicated pairs: col j stored as (b,b)
    int m0 = blockIdx.y * 128;
    int n0 = blockIdx.x * 128;
    int tid = threadIdx.x;
    int tx = tid & 15, ty = tid >> 4;
    int ar = tid & 127, ak = (tid >> 7) << 2;
    int brr = tid >> 5, bc = tid & 31;

    const float* Aptr = A + (size_t)(m0 + ar) * lda;
    int ktiles = (K + BK - 1) / BK;

    unsigned long long acc[4][8];
    #pragma unroll
    for (int i = 0; i < 4; i++)
        #pragma unroll
        for (int j = 0; j < 8; j++) acc[i][j] = 0ull;

    {   // prologue
        float4 av = *(const float4*)(Aptr + ak);
        As[0][ak + 0][ar] = av.x; As[0][ak + 1][ar] = av.y;
        As[0][ak + 2][ar] = av.z; As[0][ak + 3][ar] = av.w;
        #pragma unroll
        for (int i = 0; i < 4; i++) {
            int nn = n0 + bc + 32 * i;
            float v = (brr < K && nn < N) ? B[brr * N + nn] : 0.f;
            *(float2*)&Bs2[0][brr][2 * (bc + 32 * i)] = make_float2(v, v);
        }
    }
    __syncthreads();

    for (int t = 0; t < ktiles; t++) {
        int cur = t & 1;
        bool more = (t + 1 < ktiles);
        float4 av;
        float bv[4];
        if (more) {
            int k0 = (t + 1) * BK;
            av = *(const float4*)(Aptr + k0 + ak);
            #pragma unroll
            for (int i = 0; i < 4; i++) {
                int kk = k0 + brr, nn = n0 + bc + 32 * i;
                bv[i] = (kk < K && nn < N) ? B[kk * N + nn] : 0.f;
            }
        }
        #pragma unroll
        for (int k = 0; k < BK; k++) {
            const ulonglong2* ap = (const ulonglong2*)&As[cur][k][ty * 8];
            ulonglong2 a01 = ap[0], a23 = ap[1];
            unsigned long long a2[4] = {a01.x, a01.y, a23.x, a23.y};
            const ulonglong2* bp = (const ulonglong2*)&Bs2[cur][k][tx * 16];
            ulonglong2 b01 = bp[0], b23 = bp[1], b45 = bp[2], b67 = bp[3];
            unsigned long long b2[8] = {b01.x, b01.y, b23.x, b23.y,
                                        b45.x, b45.y, b67.x, b67.y};
            #pragma unroll
            for (int ip = 0; ip < 4; ip++)
                #pragma unroll
                for (int j = 0; j < 8; j++) fma2(acc[ip][j], a2[ip], b2[j]);
        }
        if (more) {
            int nxt = cur ^ 1;
            As[nxt][ak + 0][ar] = av.x; As[nxt][ak + 1][ar] = av.y;
            As[nxt][ak + 2][ar] = av.z; As[nxt][ak + 3][ar] = av.w;
            #pragma unroll
            for (int i = 0; i < 4; i++)
                *(float2*)&Bs2[nxt][brr][2 * (bc + 32 * i)] = make_float2(bv[i], bv[i]);
            __syncthreads();
        }
    }

    #pragma unroll
    for (int ip = 0; ip < 4; ip++) {
        int r0 = m0 + ty * 8 + 2 * ip;
        int r1 = r0 + 1;
        float d0 = 1.f, d1 = 1.f;
        if (PRESCALE) {
            if (r0 < M) d0 = dinv[r0];
            if (r1 < M) d1 = dinv[r1];
        }
        #pragma unroll
        for (int j = 0; j < 8; j++) {
            int nn = n0 + tx * 8 + j;
            if (nn >= N) continue;
            U2 u; u.u = acc[ip][j];
            float bsv = bias[nn];
            float v0 = u.f.x + bsv;
            float v1 = u.f.y + bsv;
            if (RELU) { v0 = fmaxf(v0, 0.f); v1 = fmaxf(v1, 0.f); }
            if (PRESCALE) { v0 *= d0; v1 *= d1; }
            if (r0 < M) C[(size_t)r0 * ldc + nn] = v0;
            if (r1 < M) C[(size_t)r1 * ldc + nn] = v1;
        }
    }
}

static void gemm_node(const float* A, int lda, const float* B, const float* bias,
                      const float* dinv, float* C, int ldc, int M, int N, int K,
                      bool prescale) {
    dim3 grid((N + 127) / 128, (M + 127) / 128);
    if (prescale) k_gemm128<true, true><<<grid, 256>>>(A, lda, B, bias, dinv, C, ldc, M, N, K);
    else          k_gemm128<true, false><<<grid, 256>>>(A, lda, B, bias, dinv, C, ldc, M, N, K);
}

// -------- small SGEMM (64x64, BK=16) with optional split-K --------
template <bool RELU, bool PARTIAL>
__global__ void k_sgemm64(const float* __restrict__ A, int lda,
                          const float* __restrict__ B,
                          const float* __restrict__ bias,
                          float* __restrict__ C, int ldc,
                          int M, int N, int K, int Kc) {
    const int BM = 64, BN = 64, BK = 16;
    __shared__ float As[BK][BM];
    __shared__ float Bs[BK][BN];
    int m0 = blockIdx.y * BM;
    int n0 = blockIdx.x * BN;
    int s  = blockIdx.z;
    int kbeg = PARTIAL ? s * Kc : 0;
    int kend = PARTIAL ? min(K, kbeg + Kc) : K;
    int tid = threadIdx.x;
    int tx = tid & 15, ty = tid >> 4;
    float acc[4][4] = {};
    for (int k0 = kbeg; k0 < kend; k0 += BK) {
        #pragma unroll
        for (int i = 0; i < 4; i++) {
            int l = tid + 256 * i;
            int r = l >> 4, c = l & 15;
            int mm = m0 + r, kk = k0 + c;
            As[c][r] = (mm < M && kk < kend) ? A[mm * lda + kk] : 0.f;
        }
        #pragma unroll
        for (int i = 0; i < 4; i++) {
            int l = tid + 256 * i;
            int r = l >> 6, c = l & 63;
            int kk = k0 + r, nn = n0 + c;
            Bs[r][c] = (kk < kend && nn < N) ? B[kk * N + nn] : 0.f;
        }
        __syncthreads();
        #pragma unroll
        for (int kk = 0; kk < BK; kk++) {
            float a[4], b[4];
            #pragma unroll
            for (int i = 0; i < 4; i++) a[i] = As[kk][ty * 4 + i];
            #pragma unroll
            for (int j = 0; j < 4; j++) b[j] = Bs[kk][tx * 4 + j];
            #pragma unroll
            for (int i = 0; i < 4; i++)
                #pragma unroll
                for (int j = 0; j < 4; j++) acc[i][j] += a[i] * b[j];
        }
        __syncthreads();
    }
    #pragma unroll
    for (int i = 0; i < 4; i++) {
        int mm = m0 + ty * 4 + i;
        if (mm >= M) continue;
        #pragma unroll
        for (int j = 0; j < 4; j++) {
            int nn = n0 + tx * 4 + j;
            if (nn >= N) continue;
            if (PARTIAL) {
                C[(size_t)s * M * N + mm * N + nn] = acc[i][j];
            } else {
                float v = acc[i][j] + bias[nn];
                if (RELU) v = fmaxf(v, 0.f);
                C[mm * ldc + nn] = v;
            }
        }
    }
}

template <bool RELU>
__global__ void k_reduce(const float* __restrict__ part, int S,
                         const float* __restrict__ bias,
                         float* __restrict__ C, int ldc, int M, int N) {
    int i = blockIdx.x * blockDim.x + threadIdx.x;
    if (i >= M * N) return;
    int m = i / N, n = i % N;
    float v = 0.f;
    for (int s = 0; s < S; s++) v += part[(size_t)s * M * N + i];
    v += bias[n];
    if (RELU) v = fmaxf(v, 0.f);
    C[m * ldc + n] = v;
}

static void sgemm_split(const float* A, int lda, const float* B, const float* bias,
                        float* C, int ldc, int M, int N, int K, int S, bool relu,
                        float* part) {
    int Kc = (K + S - 1) / S;
    dim3 grid((N + 63) / 64, (M + 63) / 64, S);
    k_sgemm64<false, true><<<grid, 256>>>(A, lda, B, nullptr, part, 0, M, N, K, Kc);
    int tot = M * N;
    if (relu) k_reduce<true><<<(tot + 255) / 256, 256>>>(part, S, bias, C, ldc, M, N);
    else      k_reduce<false><<<(tot + 255) / 256, 256>>>(part, S, bias, C, ldc, M, N);
}

static void sgemm_small(const float* A, int lda, const float* B, const float* bias,
                        float* C, int ldc, int M, int N, int K, bool relu) {
    dim3 grid((N + 63) / 64, (M + 63) / 64, 1);
    if (relu) k_sgemm64<true, false><<<grid, 256>>>(A, lda, B, bias, C, ldc, M, N, K, K);
    else      k_sgemm64<false, false><<<grid, 256>>>(A, lda, B, bias, C, ldc, M, N, K, K);
}

extern "C" void kernel_launch(void* const* d_in, const int* in_sizes, int n_in,
                              void* d_out, int out_size) {
    const float* x1   = (const float*)d_in[0];
    const int*   ei1  = (const int*)d_in[1];
    const int*   bat1 = (const int*)d_in[2];
    const float* x2   = (const float*)d_in[3];
    const int*   ei2  = (const int*)d_in[4];
    const int*   bat2 = (const int*)d_in[5];
    const float* cell = (const float*)d_in[6];
    const float* Wc1 = (const float*)d_in[7];  const float* bc1 = (const float*)d_in[8];
    const float* Wc2 = (const float*)d_in[9];  const float* bc2 = (const float*)d_in[10];
    const float* Wc3 = (const float*)d_in[11]; const float* bc3 = (const float*)d_in[12];
    const float* Wg1 = (const float*)d_in[13]; const float* bg1 = (const float*)d_in[14];
    const float* Wg2 = (const float*)d_in[15]; const float* bg2 = (const float*)d_in[16];
    const float* Wr1 = (const float*)d_in[17]; const float* br1 = (const float*)d_in[18];
    const float* Wr2 = (const float*)d_in[19]; const float* br2 = (const float*)d_in[20];
    const float* Wr3 = (const float*)d_in[21]; const float* br3 = (const float*)d_in[22];
    const float* Wf1 = (const float*)d_in[23]; const float* bf1 = (const float*)d_in[24];
    const float* Wf2 = (const float*)d_in[25]; const float* bf2 = (const float*)d_in[26];
    const float* Wf3 = (const float*)d_in[27]; const float* bf3 = (const float*)d_in[28];
    const float* Wo  = (const float*)d_in[29]; const float* bo  = (const float*)d_in[30];
    float* out = (float*)d_out;

    float *bufA, *bufP, *bufQ, *bufB, *dinv, *pool, *xc, *t0, *t1, *part;
    int *work, *offs, *csr;
    cudaGetSymbolAddress((void**)&bufA, g_bufA);
    cudaGetSymbolAddress((void**)&bufP, g_bufP);
    cudaGetSymbolAddress((void**)&bufQ, g_bufQ);
    cudaGetSymbolAddress((void**)&bufB, g_bufB);
    cudaGetSymbolAddress((void**)&work, g_work);
    cudaGetSymbolAddress((void**)&offs, g_offs);
    cudaGetSymbolAddress((void**)&csr,  g_csr);
    cudaGetSymbolAddress((void**)&dinv, g_dinv);
    cudaGetSymbolAddress((void**)&pool, g_pool);
    cudaGetSymbolAddress((void**)&xc,   g_xc);
    cudaGetSymbolAddress((void**)&t0,   g_t0);
    cudaGetSymbolAddress((void**)&t1,   g_t1);
    cudaGetSymbolAddress((void**)&part, g_part);
    int* cnt  = work;
    int* fill = work + N2;

    const int EB2 = (E2 + 255) / 256;
    const int AGGB = (N2 * 32 + 255) / 256;

    // ---- CSR build (launches 1-4)
    cudaMemsetAsync(work, 0, 2 * N2 * sizeof(int));
    k_count2<<<EB2, 256>>>(ei1, ei2, cnt);
    k_scan_dinv<<<1, 1024>>>(cnt, offs, dinv);
    k_fill2<<<EB2, 256>>>(ei1, ei2, offs, fill, csr);

    // ---- GCN layers (M = 40000). launch 5: agg1; launch 6: GEMM1 (profiled)
    k_agg_l1<<<AGGB, 256>>>(x1, x2, offs, csr, dinv, bufA);
    gemm_node(bufA, 80, Wc1, bc1, dinv, bufP, 80, N2, 78, 78, true);    // prescaled out
    k_agg_pre<<<AGGB, 256>>>(bufP, offs, csr, dinv, bufA);
    gemm_node(bufA, 80, Wc2, bc2, dinv, bufQ, 160, N2, 156, 78, true);  // prescaled out
    k_agg_pre2<<<AGGB, 256>>>(bufQ, offs, csr, dinv, bufA);
    gemm_node(bufA, 160, Wc3, bc3, dinv, bufB, 312, N2, 312, 156, false);

    // ---- global max pool -> [2G, 312]
    cudaMemsetAsync(pool, 0, 2 * GG * 312 * sizeof(float));
    int pthreads = (N2 / 32) * 312;
    k_pool<<<(pthreads + 255) / 256, 256>>>(bufB, bat1, bat2, pool);

    // ---- branch MLP batched (M = 512)
    sgemm_split(pool, 312, Wg1, bg1, t0, 156, 2 * GG, 156, 312, 4, true, part);
    sgemm_split(t0, 156, Wg2, bg2, t1, 128, 2 * GG, 128, 156, 2, false, part);
    k_scatter<<<(2 * GG * 128 + 255) / 256, 256>>>(t1, xc);

    // ---- cell reduction MLP -> xc cols [256..512)
    k_norm<<<GG, 256>>>(cell, t0);
    sgemm_split(t0, 954, Wr1, br1, t1, 2048, GG, 2048, 954, 2, true, part);
    sgemm_split(t1, 2048, Wr2, br2, t0, 512, GG, 512, 2048, 8, true, part);
    sgemm_split(t0, 512, Wr3, br3, xc + 256, 512, GG, 256, 512, 4, true, part);

    // ---- head MLP
    sgemm_split(xc, 512, Wf1, bf1, t0, 1024, GG, 1024, 512, 2, true, part);
    sgemm_split(t0, 1024, Wf2, bf2, t1, 512, GG, 512, 1024, 4, true, part);
    sgemm_split(t1, 512, Wf3, bf3, t0, 128, GG, 128, 512, 4, true, part);
    sgemm_small(t0, 128, Wo, bo, out, 2, GG, 2, 128, false);
}

// round 5
// speedup vs baseline: 1.9538x; 1.9538x over previous
#include <cuda_runtime.h>
#include <cstdint>

#define NN 20000
#define EE 320000
#define GG 256
#define N2 (2 * NN)
#define E2 (2 * EE)

// -------- scratch (static device globals; zero-init, no runtime allocation) --------
__device__ float g_bufA[(N2 + 256) * 160];   // agg outputs / GEMM A (pads stay 0)
__device__ float g_bufP[(N2 + 256) * 80];    // prescaled h (layer-2 input)
__device__ float g_bufQ[(N2 + 256) * 160];   // prescaled h (layer-3 input)
__device__ float g_bufB[(N2 + 256) * 312];   // layer-3 output (pool input)
__device__ int   g_work[2 * N2];             // cnt | fill
__device__ int   g_offs[N2 + 1];
__device__ int   g_csr[E2];
__device__ float g_dinv[N2];
__device__ float g_pool[2 * GG * 312];
__device__ float g_xc[GG * 512];
__device__ float g_t0[2 * GG * 2048];
__device__ float g_t1[2 * GG * 2048];
__device__ float g_part[8 * GG * 1024];

// -------- tf32 helpers --------
__device__ __forceinline__ void tf32split(float v, uint32_t& hi, uint32_t& lo) {
    asm("cvt.rna.tf32.f32 %0, %1;" : "=r"(hi) : "f"(v));
    float r = v - __uint_as_float(hi);
    asm("cvt.rna.tf32.f32 %0, %1;" : "=r"(lo) : "f"(r));
}
__device__ __forceinline__ void mma8(float* c, const uint32_t* a, const uint32_t* b) {
    asm("mma.sync.aligned.m16n8k8.row.col.f32.tf32.tf32.f32 "
        "{%0,%1,%2,%3}, {%4,%5,%6,%7}, {%8,%9}, {%0,%1,%2,%3};"
        : "+f"(c[0]), "+f"(c[1]), "+f"(c[2]), "+f"(c[3])
        : "r"(a[0]), "r"(a[1]), "r"(a[2]), "r"(a[3]), "r"(b[0]), "r"(b[1]));
}

// -------- CSR build over combined graph --------
__global__ void k_count2(const int* __restrict__ ei1, const int* __restrict__ ei2,
                         int* __restrict__ cnt) {
    int e = blockIdx.x * blockDim.x + threadIdx.x;
    if (e < EE) atomicAdd(&cnt[ei1[EE + e]], 1);
    else if (e < E2) atomicAdd(&cnt[ei2[EE + (e - EE)] + NN], 1);
}

__global__ void k_scan_dinv(const int* __restrict__ cnt, int* __restrict__ offs,
                            float* __restrict__ dinv) {
    const int T = 1024;
    const int IPT = (N2 + T - 1) / T;
    __shared__ int s[T];
    int tid = threadIdx.x;
    int base = tid * IPT;
    int local = 0;
    #pragma unroll
    for (int i = 0; i < IPT; i++) {
        int idx = base + i;
        if (idx < N2) {
            int c = cnt[idx];
            local += c;
            dinv[idx] = rsqrtf((float)(c + 1));
        }
    }
    s[tid] = local;
    __syncthreads();
    for (int off = 1; off < T; off <<= 1) {
        int v = 0;
        if (tid >= off) v = s[tid - off];
        __syncthreads();
        if (tid >= off) s[tid] += v;
        __syncthreads();
    }
    int run = (tid == 0) ? 0 : s[tid - 1];
    #pragma unroll
    for (int i = 0; i < IPT; i++) {
        int idx = base + i;
        if (idx < N2) { offs[idx] = run; run += cnt[idx]; }
    }
    if (tid == 0) offs[N2] = s[T - 1];
}

__global__ void k_fill2(const int* __restrict__ ei1, const int* __restrict__ ei2,
                        const int* __restrict__ offs, int* __restrict__ fill,
                        int* __restrict__ csr) {
    int e = blockIdx.x * blockDim.x + threadIdx.x;
    int s, d;
    if (e < EE) { s = ei1[e]; d = ei1[EE + e]; }
    else if (e < E2) { s = ei2[e - EE] + NN; d = ei2[EE + (e - EE)] + NN; }
    else return;
    int p = atomicAdd(&fill[d], 1);
    csr[offs[d] + p] = s;
}

// -------- layer-1 aggregation (raw x1/x2, dinv inside) --------
__global__ void k_agg_l1(const float* __restrict__ h0, const float* __restrict__ h1,
                         const int* __restrict__ offs, const int* __restrict__ csr,
                         const float* __restrict__ dinv, float* __restrict__ out) {
    int warp = (blockIdx.x * blockDim.x + threadIdx.x) >> 5;
    int lane = threadIdx.x & 31;
    if (warp >= N2) return;
    int n = warp;
    const float* hn = (n < NN) ? h0 + (size_t)n * 78 : h1 + (size_t)(n - NN) * 78;
    float din = dinv[n];
    float acc[3];
    #pragma unroll
    for (int r = 0; r < 3; r++) {
        int f = lane + 32 * r;
        acc[r] = (f < 78) ? din * hn[f] : 0.f;
    }
    int e0 = offs[n], e1 = offs[n + 1];
    for (int e = e0; e < e1; e++) {
        int s = csr[e];
        const float* hs = (s < NN) ? h0 + (size_t)s * 78 : h1 + (size_t)(s - NN) * 78;
        float ds = dinv[s];
        #pragma unroll
        for (int r = 0; r < 3; r++) {
            int f = lane + 32 * r;
            if (f < 78) acc[r] += ds * hs[f];
        }
    }
    #pragma unroll
    for (int r = 0; r < 3; r++) {
        int f = lane + 32 * r;
        if (f < 78) out[(size_t)n * 80 + f] = din * acc[r];
    }
}

// -------- prescaled scalar aggregation (layer-2, DIM=78, ld 80) --------
__global__ void k_agg_pre(const float* __restrict__ hp, const int* __restrict__ offs,
                          const int* __restrict__ csr, const float* __restrict__ dinv,
                          float* __restrict__ out) {
    int warp = (blockIdx.x * blockDim.x + threadIdx.x) >> 5;
    int lane = threadIdx.x & 31;
    if (warp >= N2) return;
    int n = warp;
    float acc[3];
    #pragma unroll
    for (int r = 0; r < 3; r++) {
        int f = lane + 32 * r;
        acc[r] = (f < 78) ? hp[(size_t)n * 80 + f] : 0.f;
    }
    int e0 = offs[n], e1 = offs[n + 1];
    int e = e0;
    for (; e + 2 <= e1; e += 2) {
        int s0 = csr[e], s1 = csr[e + 1];
        const float* p0 = hp + (size_t)s0 * 80;
        const float* p1 = hp + (size_t)s1 * 80;
        #pragma unroll
        for (int r = 0; r < 3; r++) {
            int f = lane + 32 * r;
            if (f < 78) acc[r] += p0[f] + p1[f];
        }
    }
    if (e < e1) {
        const float* p0 = hp + (size_t)csr[e] * 80;
        #pragma unroll
        for (int r = 0; r < 3; r++) {
            int f = lane + 32 * r;
            if (f < 78) acc[r] += p0[f];
        }
    }
    float din = dinv[n];
    #pragma unroll
    for (int r = 0; r < 3; r++) {
        int f = lane + 32 * r;
        if (f < 78) out[(size_t)n * 80 + f] = din * acc[r];
    }
}

// -------- prescaled float2 aggregation (layer-3, DIM=156, ld 160) --------
__global__ void k_agg_pre2(const float* __restrict__ hp, const int* __restrict__ offs,
                           const int* __restrict__ csr, const float* __restrict__ dinv,
                           float* __restrict__ out) {
    int warp = (blockIdx.x * blockDim.x + threadIdx.x) >> 5;
    int lane = threadIdx.x & 31;
    if (warp >= N2) return;
    int n = warp;
    const float2* pn = (const float2*)(hp + (size_t)n * 160);
    float2 acc[3];
    #pragma unroll
    for (int r = 0; r < 3; r++) {
        int idx = lane + 32 * r;
        acc[r] = (idx < 78) ? pn[idx] : make_float2(0.f, 0.f);
    }
    int e0 = offs[n], e1 = offs[n + 1];
    int e = e0;
    for (; e + 2 <= e1; e += 2) {
        int s0 = csr[e], s1 = csr[e + 1];
        const float2* p0 = (const float2*)(hp + (size_t)s0 * 160);
        const float2* p1 = (const float2*)(hp + (size_t)s1 * 160);
        #pragma unroll
        for (int r = 0; r < 3; r++) {
            int idx = lane + 32 * r;
            if (idx < 78) {
                float2 v0 = p0[idx], v1 = p1[idx];
                acc[r].x += v0.x + v1.x;
                acc[r].y += v0.y + v1.y;
            }
        }
    }
    if (e < e1) {
        const float2* p0 = (const float2*)(hp + (size_t)csr[e] * 160);
        #pragma unroll
        for (int r = 0; r < 3; r++) {
            int idx = lane + 32 * r;
            if (idx < 78) {
                float2 v0 = p0[idx];
                acc[r].x += v0.x;
                acc[r].y += v0.y;
            }
        }
    }
    float din = dinv[n];
    float2* po = (float2*)(out + (size_t)n * 160);
    #pragma unroll
    for (int r = 0; r < 3; r++) {
        int idx = lane + 32 * r;
        if (idx < 78) po[idx] = make_float2(din * acc[r].x, din * acc[r].y);
    }
}

// -------- global max pool --------
__global__ void k_pool(const float* __restrict__ h,
                       const int* __restrict__ bat1, const int* __restrict__ bat2,
                       float* __restrict__ pool) {
    const int CH = 32;
    const int NCH = N2 / CH;
    int idx = blockIdx.x * blockDim.x + threadIdx.x;
    if (idx >= NCH * 312) return;
    int f = idx % 312;
    int c = idx / 312;
    int n0 = c * CH;
    int n1 = n0 + CH;
    int curb = (n0 < NN) ? bat1[n0] : GG + bat2[n0 - NN];
    float m = 0.f;
    for (int n = n0; n < n1; n++) {
        int b = (n < NN) ? bat1[n] : GG + bat2[n - NN];
        if (b != curb) {
            atomicMax((int*)&pool[curb * 312 + f], __float_as_int(m));
            curb = b;
            m = 0.f;
        }
        m = fmaxf(m, h[(size_t)n * 312 + f]);
    }
    atomicMax((int*)&pool[curb * 312 + f], __float_as_int(m));
}

// -------- scatter branch-MLP output [2G,128] -> xc[G,512] --------
__global__ void k_scatter(const float* __restrict__ t, float* __restrict__ xc) {
    int i = blockIdx.x * blockDim.x + threadIdx.x;
    if (i >= 2 * GG * 128) return;
    int r = i >> 7, j = i & 127;
    int br = r >> 8;
    int g = r & 255;
    xc[g * 512 + br * 128 + j] = t[i];
}

// -------- L2 row normalize --------
__global__ void k_norm(const float* __restrict__ cell, float* __restrict__ out) {
    int g = blockIdx.x;
    __shared__ float s[256];
    float ss = 0.f;
    for (int j = threadIdx.x; j < 954; j += 256) {
        float v = cell[g * 954 + j];
        ss += v * v;
    }
    s[threadIdx.x] = ss;
    __syncthreads();
    for (int o = 128; o > 0; o >>= 1) {
        if (threadIdx.x < o) s[threadIdx.x] += s[threadIdx.x + o];
        __syncthreads();
    }
    float inv = 1.f / fmaxf(sqrtf(s[0]), 1e-12f);
    for (int j = threadIdx.x; j < 954; j += 256)
        out[g * 954 + j] = cell[g * 954 + j] * inv;
}

// ======== tensor-core node GEMM: mma.m16n8k8.tf32 with 3xTF32 split ========
// C[M,N] = A[M,Kp](lda) @ B[Kr,N] + bias, relu, optional dinv row prescale.
// Kp = K padded to mult of 16 (A pad cols are zero); B loads guarded by Kr.
// Block 128x64, BK=16 double-buffered, 8 warps of 32x32 (2x4 m16n8 tiles).
template <bool RELU, bool PRESCALE>
__global__ __launch_bounds__(256)
void k_tgemm(const float* __restrict__ A, int lda,
             const float* __restrict__ B,
             const float* __restrict__ bias,
             const float* __restrict__ dinv,
             float* __restrict__ C, int ldc,
             int M, int N, int Kp, int Kr) {
    const int BM = 128, BN = 64, BK = 16;
    __shared__ float As[2][BK][BM + 8];   // [k][m]
    __shared__ float Bs[2][BK][BN + 8];   // [k][n]
    int tid = threadIdx.x;
    int lane = tid & 31, wid = tid >> 5;
    int gid = lane >> 2, tq = lane & 3;
    int wm = (wid & 3) * 32, wn = (wid >> 2) * 32;
    int m0 = blockIdx.y * BM, n0 = blockIdx.x * BN;

    // A load mapping: row = tid&127 (32 distinct rows per warp -> conflict-free STS)
    int arow = tid & 127;
    int akq = (tid >> 7) * 4;             // 0 or 4; second slot at +8
    const float* Ar = A + (size_t)(m0 + arow) * lda;

    float acc[2][4][4];
    #pragma unroll
    for (int i = 0; i < 2; i++)
        #pragma unroll
        for (int j = 0; j < 4; j++)
            #pragma unroll
            for (int r = 0; r < 4; r++) acc[i][j][r] = 0.f;

    int ksteps = Kp / BK;

    // prologue: stage 0 -> buffer 0
    {
        float4 a0 = *(const float4*)(Ar + akq);
        float4 a1 = *(const float4*)(Ar + akq + 8);
        As[0][akq + 0][arow] = a0.x; As[0][akq + 1][arow] = a0.y;
        As[0][akq + 2][arow] = a0.z; As[0][akq + 3][arow] = a0.w;
        As[0][akq + 8][arow] = a1.x; As[0][akq + 9][arow] = a1.y;
        As[0][akq + 10][arow] = a1.z; As[0][akq + 11][arow] = a1.w;
        #pragma unroll
        for (int i = 0; i < 4; i++) {
            int l = tid + 256 * i;
            int bk = l >> 6, bn = l & 63;
            int nn = n0 + bn;
            Bs[0][bk][bn] = (bk < Kr && nn < N) ? B[bk * N + nn] : 0.f;
        }
    }
    __syncthreads();

    for (int t = 0; t < ksteps; t++) {
        int cur = t & 1;
        bool more = (t + 1 < ksteps);
        float4 pa0, pa1;
        float pb[4];
        if (more) {
            int k0 = (t + 1) * BK;
            pa0 = *(const float4*)(Ar + k0 + akq);
            pa1 = *(const float4*)(Ar + k0 + akq + 8);
            #pragma unroll
            for (int i = 0; i < 4; i++) {
                int l = tid + 256 * i;
                int bk = l >> 6, bn = l & 63;
                int nn = n0 + bn;
                pb[i] = (k0 + bk < Kr && nn < N) ? B[(k0 + bk) * N + nn] : 0.f;
            }
        }
        #pragma unroll
        for (int k8 = 0; k8 < 2; k8++) {
            int kb = k8 * 8;
            uint32_t ah[2][4], al[2][4];
            #pragma unroll
            for (int mi = 0; mi < 2; mi++) {
                int r = wm + mi * 16 + gid;
                int c = kb + tq;
                float v0 = As[cur][c][r];
                float v1 = As[cur][c][r + 8];
                float v2 = As[cur][c + 4][r];
                float v3 = As[cur][c + 4][r + 8];
                tf32split(v0, ah[mi][0], al[mi][0]);
                tf32split(v1, ah[mi][1], al[mi][1]);
                tf32split(v2, ah[mi][2], al[mi][2]);
                tf32split(v3, ah[mi][3], al[mi][3]);
            }
            uint32_t bh[4][2], bl[4][2];
            #pragma unroll
            for (int ni = 0; ni < 4; ni++) {
                int cc = wn + ni * 8 + gid;
                float w0 = Bs[cur][kb + tq][cc];
                float w1 = Bs[cur][kb + tq + 4][cc];
                tf32split(w0, bh[ni][0], bl[ni][0]);
                tf32split(w1, bh[ni][1], bl[ni][1]);
            }
            #pragma unroll
            for (int mi = 0; mi < 2; mi++)
                #pragma unroll
                for (int ni = 0; ni < 4; ni++) {
                    mma8(acc[mi][ni], ah[mi], bh[ni]);
                    mma8(acc[mi][ni], al[mi], bh[ni]);
                    mma8(acc[mi][ni], ah[mi], bl[ni]);
                }
        }
        if (more) {
            int nxt = cur ^ 1;
            As[nxt][akq + 0][arow] = pa0.x; As[nxt][akq + 1][arow] = pa0.y;
            As[nxt][akq + 2][arow] = pa0.z; As[nxt][akq + 3][arow] = pa0.w;
            As[nxt][akq + 8][arow] = pa1.x; As[nxt][akq + 9][arow] = pa1.y;
            As[nxt][akq + 10][arow] = pa1.z; As[nxt][akq + 11][arow] = pa1.w;
            #pragma unroll
            for (int i = 0; i < 4; i++) {
                int l = tid + 256 * i;
                Bs[nxt][l >> 6][l & 63] = pb[i];
            }
            __syncthreads();
        }
    }

    // epilogue: rows gid / gid+8 per m16 tile, col pairs 2*tq, 2*tq+1 (N always even)
    #pragma unroll
    for (int mi = 0; mi < 2; mi++) {
        int r0 = m0 + wm + mi * 16 + gid;
        int r1 = r0 + 8;
        float d0 = 1.f, d1 = 1.f;
        if (PRESCALE) {
            if (r0 < M) d0 = dinv[r0];
            if (r1 < M) d1 = dinv[r1];
        }
        #pragma unroll
        for (int ni = 0; ni < 4; ni++) {
            int cc = n0 + wn + ni * 8 + 2 * tq;
            if (cc >= N) continue;
            float b0 = bias[cc], b1 = bias[cc + 1];
            float* a = acc[mi][ni];
            float v00 = a[0] + b0, v01 = a[1] + b1;
            float v10 = a[2] + b0, v11 = a[3] + b1;
            if (RELU) {
                v00 = fmaxf(v00, 0.f); v01 = fmaxf(v01, 0.f);
                v10 = fmaxf(v10, 0.f); v11 = fmaxf(v11, 0.f);
            }
            if (PRESCALE) { v00 *= d0; v01 *= d0; v10 *= d1; v11 *= d1; }
            if (r0 < M) *(float2*)&C[(size_t)r0 * ldc + cc] = make_float2(v00, v01);
            if (r1 < M) *(float2*)&C[(size_t)r1 * ldc + cc] = make_float2(v10, v11);
        }
    }
}

static void gemm_node(const float* A, int lda, const float* B, const float* bias,
                      const float* dinv, float* C, int ldc, int M, int N,
                      int Kp, int Kr, bool prescale) {
    dim3 grid((N + 63) / 64, (M + 127) / 128);
    if (prescale)
        k_tgemm<true, true><<<grid, 256>>>(A, lda, B, bias, dinv, C, ldc, M, N, Kp, Kr);
    else
        k_tgemm<true, false><<<grid, 256>>>(A, lda, B, bias, dinv, C, ldc, M, N, Kp, Kr);
}

// -------- small SGEMM (64x64, BK=16) with optional split-K --------
template <bool RELU, bool PARTIAL>
__global__ void k_sgemm64(const float* __restrict__ A, int lda,
                          const float* __restrict__ B,
                          const float* __restrict__ bias,
                          float* __restrict__ C, int ldc,
                          int M, int N, int K, int Kc) {
    const int BM = 64, BN = 64, BK = 16;
    __shared__ float As[BK][BM];
    __shared__ float Bs[BK][BN];
    int m0 = blockIdx.y * BM;
    int n0 = blockIdx.x * BN;
    int s  = blockIdx.z;
    int kbeg = PARTIAL ? s * Kc : 0;
    int kend = PARTIAL ? min(K, kbeg + Kc) : K;
    int tid = threadIdx.x;
    int tx = tid & 15, ty = tid >> 4;
    float acc[4][4] = {};
    for (int k0 = kbeg; k0 < kend; k0 += BK) {
        #pragma unroll
        for (int i = 0; i < 4; i++) {
            int l = tid + 256 * i;
            int r = l >> 4, c = l & 15;
            int mm = m0 + r, kk = k0 + c;
            As[c][r] = (mm < M && kk < kend) ? A[mm * lda + kk] : 0.f;
        }
        #pragma unroll
        for (int i = 0; i < 4; i++) {
            int l = tid + 256 * i;
            int r = l >> 6, c = l & 63;
            int kk = k0 + r, nn = n0 + c;
            Bs[r][c] = (kk < kend && nn < N) ? B[kk * N + nn] : 0.f;
        }
        __syncthreads();
        #pragma unroll
        for (int kk = 0; kk < BK; kk++) {
            float a[4], b[4];
            #pragma unroll
            for (int i = 0; i < 4; i++) a[i] = As[kk][ty * 4 + i];
            #pragma unroll
            for (int j = 0; j < 4; j++) b[j] = Bs[kk][tx * 4 + j];
            #pragma unroll
            for (int i = 0; i < 4; i++)
                #pragma unroll
                for (int j = 0; j < 4; j++) acc[i][j] += a[i] * b[j];
        }
        __syncthreads();
    }
    #pragma unroll
    for (int i = 0; i < 4; i++) {
        int mm = m0 + ty * 4 + i;
        if (mm >= M) continue;
        #pragma unroll
        for (int j = 0; j < 4; j++) {
            int nn = n0 + tx * 4 + j;
            if (nn >= N) continue;
            if (PARTIAL) {
                C[(size_t)s * M * N + mm * N + nn] = acc[i][j];
            } else {
                float v = acc[i][j] + bias[nn];
                if (RELU) v = fmaxf(v, 0.f);
                C[mm * ldc + nn] = v;
            }
        }
    }
}

template <bool RELU>
__global__ void k_reduce(const float* __restrict__ part, int S,
                         const float* __restrict__ bias,
                         float* __restrict__ C, int ldc, int M, int N) {
    int i = blockIdx.x * blockDim.x + threadIdx.x;
    if (i >= M * N) return;
    int m = i / N, n = i % N;
    float v = 0.f;
    for (int s = 0; s < S; s++) v += part[(size_t)s * M * N + i];
    v += bias[n];
    if (RELU) v = fmaxf(v, 0.f);
    C[m * ldc + n] = v;
}

static void sgemm_split(const float* A, int lda, const float* B, const float* bias,
                        float* C, int ldc, int M, int N, int K, int S, bool relu,
                        float* part) {
    int Kc = (K + S - 1) / S;
    dim3 grid((N + 63) / 64, (M + 63) / 64, S);
    k_sgemm64<false, true><<<grid, 256>>>(A, lda, B, nullptr, part, 0, M, N, K, Kc);
    int tot = M * N;
    if (relu) k_reduce<true><<<(tot + 255) / 256, 256>>>(part, S, bias, C, ldc, M, N);
    else      k_reduce<false><<<(tot + 255) / 256, 256>>>(part, S, bias, C, ldc, M, N);
}

static void sgemm_small(const float* A, int lda, const float* B, const float* bias,
                        float* C, int ldc, int M, int N, int K, bool relu) {
    dim3 grid((N + 63) / 64, (M + 63) / 64, 1);
    if (relu) k_sgemm64<true, false><<<grid, 256>>>(A, lda, B, bias, C, ldc, M, N, K, K);
    else      k_sgemm64<false, false><<<grid, 256>>>(A, lda, B, bias, C, ldc, M, N, K, K);
}

extern "C" void kernel_launch(void* const* d_in, const int* in_sizes, int n_in,
                              void* d_out, int out_size) {
    const float* x1   = (const float*)d_in[0];
    const int*   ei1  = (const int*)d_in[1];
    const int*   bat1 = (const int*)d_in[2];
    const float* x2   = (const float*)d_in[3];
    const int*   ei2  = (const int*)d_in[4];
    const int*   bat2 = (const int*)d_in[5];
    const float* cell = (const float*)d_in[6];
    const float* Wc1 = (const float*)d_in[7];  const float* bc1 = (const float*)d_in[8];
    const float* Wc2 = (const float*)d_in[9];  const float* bc2 = (const float*)d_in[10];
    const float* Wc3 = (const float*)d_in[11]; const float* bc3 = (const float*)d_in[12];
    const float* Wg1 = (const float*)d_in[13]; const float* bg1 = (const float*)d_in[14];
    const float* Wg2 = (const float*)d_in[15]; const float* bg2 = (const float*)d_in[16];
    const float* Wr1 = (const float*)d_in[17]; const float* br1 = (const float*)d_in[18];
    const float* Wr2 = (const float*)d_in[19]; const float* br2 = (const float*)d_in[20];
    const float* Wr3 = (const float*)d_in[21]; const float* br3 = (const float*)d_in[22];
    const float* Wf1 = (const float*)d_in[23]; const float* bf1 = (const float*)d_in[24];
    const float* Wf2 = (const float*)d_in[25]; const float* bf2 = (const float*)d_in[26];
    const float* Wf3 = (const float*)d_in[27]; const float* bf3 = (const float*)d_in[28];
    const float* Wo  = (const float*)d_in[29]; const float* bo  = (const float*)d_in[30];
    float* out = (float*)d_out;

    float *bufA, *bufP, *bufQ, *bufB, *dinv, *pool, *xc, *t0, *t1, *part;
    int *work, *offs, *csr;
    cudaGetSymbolAddress((void**)&bufA, g_bufA);
    cudaGetSymbolAddress((void**)&bufP, g_bufP);
    cudaGetSymbolAddress((void**)&bufQ, g_bufQ);
    cudaGetSymbolAddress((void**)&bufB, g_bufB);
    cudaGetSymbolAddress((void**)&work, g_work);
    cudaGetSymbolAddress((void**)&offs, g_offs);
    cudaGetSymbolAddress((void**)&csr,  g_csr);
    cudaGetSymbolAddress((void**)&dinv, g_dinv);
    cudaGetSymbolAddress((void**)&pool, g_pool);
    cudaGetSymbolAddress((void**)&xc,   g_xc);
    cudaGetSymbolAddress((void**)&t0,   g_t0);
    cudaGetSymbolAddress((void**)&t1,   g_t1);
    cudaGetSymbolAddress((void**)&part, g_part);
    int* cnt  = work;
    int* fill = work + N2;

    const int EB2 = (E2 + 255) / 256;
    const int AGGB = (N2 * 32 + 255) / 256;

    // ---- CSR build
    cudaMemsetAsync(work, 0, 2 * N2 * sizeof(int));
    k_count2<<<EB2, 256>>>(ei1, ei2, cnt);
    k_scan_dinv<<<1, 1024>>>(cnt, offs, dinv);
    k_fill2<<<EB2, 256>>>(ei1, ei2, offs, fill, csr);

    // ---- GCN layers (M = 40000), tensor-core GEMMs
    k_agg_l1<<<AGGB, 256>>>(x1, x2, offs, csr, dinv, bufA);
    gemm_node(bufA, 80, Wc1, bc1, dinv, bufP, 80, N2, 78, 80, 78, true);
    k_agg_pre<<<AGGB, 256>>>(bufP, offs, csr, dinv, bufA);
    gemm_node(bufA, 80, Wc2, bc2, dinv, bufQ, 160, N2, 156, 80,78, true);
    k_agg_pre2<<<AGGB, 256>>>(bufQ, offs, csr, dinv, bufA);
    gemm_node(bufA, 160, Wc3, bc3, dinv, bufB, 312, N2, 312, 160, 156, false);

    // ---- global max pool -> [2G, 312]
    cudaMemsetAsync(pool, 0, 2 * GG * 312 * sizeof(float));
    int pthreads = (N2 / 32) * 312;
    k_pool<<<(pthreads + 255) / 256, 256>>>(bufB, bat1, bat2, pool);

    // ---- branch MLP batched (M = 512)
    sgemm_split(pool, 312, Wg1, bg1, t0, 156, 2 * GG, 156, 312, 4, true, part);
    sgemm_split(t0, 156, Wg2, bg2, t1, 128, 2 * GG, 128, 156, 2, false, part);
    k_scatter<<<(2 * GG * 128 + 255) / 256, 256>>>(t1, xc);

    // ---- cell reduction MLP -> xc cols [256..512)
    k_norm<<<GG, 256>>>(cell, t0);
    sgemm_split(t0, 954, Wr1, br1, t1, 2048, GG, 2048, 954, 2, true, part);
    sgemm_split(t1, 2048, Wr2, br2, t0, 512, GG, 512, 2048, 8, true, part);
    sgemm_split(t0, 512, Wr3, br3, xc + 256, 512, GG, 256, 512, 4, true, part);

    // ---- head MLP
    sgemm_split(xc, 512, Wf1, bf1, t0, 1024, GG, 1024, 512, 2, true, part);
    sgemm_split(t0, 1024, Wf2, bf2, t1, 512, GG, 512, 1024, 4, true, part);
    sgemm_split(t1, 512, Wf3, bf3, t0, 128, GG, 128, 512, 4, true, part);
    sgemm_small(t0, 128, Wo, bo, out, 2, GG, 2, 128, false);
}

// round 6
// speedup vs baseline: 2.1349x; 1.0927x over previous
#include <cuda_runtime.h>
#include <cuda_bf16.h>
#include <cstdint>

#define NN 20000
#define EE 320000
#define GG 256
#define N2 (2 * NN)
#define E2 (2 * EE)

// -------- scratch (static device globals; zero-init, no runtime allocation) --------
__device__ float g_bufA[(N2 + 256) * 160];   // agg outputs / GEMM A (pads stay harmless)
__device__ float g_bufP[(N2 + 256) * 80];    // prescaled h (layer-2 input)
__device__ float g_bufQ[(N2 + 256) * 160];   // prescaled h (layer-3 input)
__device__ float g_bufB[(N2 + 256) * 312];   // layer-3 output (pool input)
__device__ int   g_work[2 * N2];             // cnt | fill   (re-zeroed at end of each call)
__device__ int   g_offs[N2 + 1];
__device__ int   g_csr[E2];
__device__ float g_dinv[N2];
__device__ float g_pool[2 * GG * 312];       // re-zeroed at end of each call
__device__ float g_xc[GG * 512];
__device__ float g_t0[2 * GG * 2048];
__device__ float g_t1[2 * GG * 2048];
__device__ float g_part[8 * GG * 1024];

// -------- bf16 split helpers --------
__device__ __forceinline__ void bsplit2(float x, float y, uint32_t& hi, uint32_t& lo) {
    __nv_bfloat162 h = __floats2bfloat162_rn(x, y);          // low=x, high=y
    float rx = x - __bfloat162float(h.x);
    float ry = y - __bfloat162float(h.y);
    __nv_bfloat162 l = __floats2bfloat162_rn(rx, ry);
    hi = *reinterpret_cast<uint32_t*>(&h);
    lo = *reinterpret_cast<uint32_t*>(&l);
}
__device__ __forceinline__ void mma16(float* c, const uint32_t* a, const uint32_t* b) {
    asm("mma.sync.aligned.m16n8k16.row.col.f32.bf16.bf16.f32 "
        "{%0,%1,%2,%3}, {%4,%5,%6,%7}, {%8,%9}, {%0,%1,%2,%3};"
        : "+f"(c[0]), "+f"(c[1]), "+f"(c[2]), "+f"(c[3])
        : "r"(a[0]), "r"(a[1]), "r"(a[2]), "r"(a[3]), "r"(b[0]), "r"(b[1]));
}

// -------- CSR build over combined graph --------
__global__ void k_count2(const int* __restrict__ ei1, const int* __restrict__ ei2,
                         int* __restrict__ cnt) {
    int e = blockIdx.x * blockDim.x + threadIdx.x;
    if (e < EE) atomicAdd(&cnt[ei1[EE + e]], 1);
    else if (e < E2) atomicAdd(&cnt[ei2[EE + (e - EE)] + NN], 1);
}

__global__ void k_scan_dinv(const int* __restrict__ cnt, int* __restrict__ offs,
                            float* __restrict__ dinv) {
    const int T = 1024;
    const int IPT = (N2 + T - 1) / T;
    __shared__ int s[T];
    int tid = threadIdx.x;
    int base = tid * IPT;
    int local = 0;
    #pragma unroll
    for (int i = 0; i < IPT; i++) {
        int idx = base + i;
        if (idx < N2) {
            int c = cnt[idx];
            local += c;
            dinv[idx] = rsqrtf((float)(c + 1));
        }
    }
    s[tid] = local;
    __syncthreads();
    for (int off = 1; off < T; off <<= 1) {
        int v = 0;
        if (tid >= off) v = s[tid - off];
        __syncthreads();
        if (tid >= off) s[tid] += v;
        __syncthreads();
    }
    int run = (tid == 0) ? 0 : s[tid - 1];
    #pragma unroll
    for (int i = 0; i < IPT; i++) {
        int idx = base + i;
        if (idx < N2) { offs[idx] = run; run += cnt[idx]; }
    }
    if (tid == 0) offs[N2] = s[T - 1];
}

__global__ void k_fill2(const int* __restrict__ ei1, const int* __restrict__ ei2,
                        const int* __restrict__ offs, int* __restrict__ fill,
                        int* __restrict__ csr) {
    int e = blockIdx.x * blockDim.x + threadIdx.x;
    int s, d;
    if (e < EE) { s = ei1[e]; d = ei1[EE + e]; }
    else if (e < E2) { s = ei2[e - EE] + NN; d = ei2[EE + (e - EE)] + NN; }
    else return;
    int p = atomicAdd(&fill[d], 1);
    csr[offs[d] + p] = s;
}

// -------- layer-1 aggregation (raw x1/x2, dinv inside) --------
__global__ void k_agg_l1(const float* __restrict__ h0, const float* __restrict__ h1,
                         const int* __restrict__ offs, const int* __restrict__ csr,
                         const float* __restrict__ dinv, float* __restrict__ out) {
    int warp = (blockIdx.x * blockDim.x + threadIdx.x) >> 5;
    int lane = threadIdx.x & 31;
    if (warp >= N2) return;
    int n = warp;
    const float* hn = (n < NN) ? h0 + (size_t)n * 78 : h1 + (size_t)(n - NN) * 78;
    float din = dinv[n];
    float acc[3];
    #pragma unroll
    for (int r = 0; r < 3; r++) {
        int f = lane + 32 * r;
        acc[r] = (f < 78) ? din * hn[f] : 0.f;
    }
    int e0 = offs[n], e1 = offs[n + 1];
    for (int e = e0; e < e1; e++) {
        int s = csr[e];
        const float* hs = (s < NN) ? h0 + (size_t)s * 78 : h1 + (size_t)(s - NN) * 78;
        float ds = dinv[s];
        #pragma unroll
        for (int r = 0; r < 3; r++) {
            int f = lane + 32 * r;
            if (f < 78) acc[r] += ds * hs[f];
        }
    }
    #pragma unroll
    for (int r = 0; r < 3; r++) {
        int f = lane + 32 * r;
        if (f < 78) out[(size_t)n * 80 + f] = din * acc[r];
    }
}

// -------- prescaled scalar aggregation (layer-2, DIM=78, ld 80) --------
__global__ void k_agg_pre(const float* __restrict__ hp, const int* __restrict__ offs,
                          const int* __restrict__ csr, const float* __restrict__ dinv,
                          float* __restrict__ out) {
    int warp = (blockIdx.x * blockDim.x + threadIdx.x) >> 5;
    int lane = threadIdx.x & 31;
    if (warp >= N2) return;
    int n = warp;
    float acc[3];
    #pragma unroll
    for (int r = 0; r < 3; r++) {
        int f = lane + 32 * r;
        acc[r] = (f < 78) ? hp[(size_t)n * 80 + f] : 0.f;
    }
    int e0 = offs[n], e1 = offs[n + 1];
    int e = e0;
    for (; e + 2 <= e1; e += 2) {
        int s0 = csr[e], s1 = csr[e + 1];
        const float* p0 = hp + (size_t)s0 * 80;
        const float* p1 = hp + (size_t)s1 * 80;
        #pragma unroll
        for (int r = 0; r < 3; r++) {
            int f = lane + 32 * r;
            if (f < 78) acc[r] += p0[f] + p1[f];
        }
    }
    if (e < e1) {
        const float* p0 = hp + (size_t)csr[e] * 80;
        #pragma unroll
        for (int r = 0; r < 3; r++) {
            int f = lane + 32 * r;
            if (f < 78) acc[r] += p0[f];
        }
    }
    float din = dinv[n];
    #pragma unroll
    for (int r = 0; r < 3; r++) {
        int f = lane + 32 * r;
        if (f < 78) out[(size_t)n * 80 + f] = din * acc[r];
    }
}

// -------- prescaled float2 aggregation (layer-3, DIM=156, ld 160) --------
__global__ void k_agg_pre2(const float* __restrict__ hp, const int* __restrict__ offs,
                           const int* __restrict__ csr, const float* __restrict__ dinv,
                           float* __restrict__ out) {
    int warp = (blockIdx.x * blockDim.x + threadIdx.x) >> 5;
    int lane = threadIdx.x & 31;
    if (warp >= N2) return;
    int n = warp;
    const float2* pn = (const float2*)(hp + (size_t)n * 160);
    float2 acc[3];
    #pragma unroll
    for (int r = 0; r < 3; r++) {
        int idx = lane + 32 * r;
        acc[r] = (idx < 78) ? pn[idx] : make_float2(0.f, 0.f);
    }
    int e0 = offs[n], e1 = offs[n + 1];
    int e = e0;
    for (; e + 2 <= e1; e += 2) {
        int s0 = csr[e], s1 = csr[e + 1];
        const float2* p0 = (const float2*)(hp + (size_t)s0 * 160);
        const float2* p1 = (const float2*)(hp + (size_t)s1 * 160);
        #pragma unroll
        for (int r = 0; r < 3; r++) {
            int idx = lane + 32 * r;
            if (idx < 78) {
                float2 v0 = p0[idx], v1 = p1[idx];
                acc[r].x += v0.x + v1.x;
                acc[r].y += v0.y + v1.y;
            }
        }
    }
    if (e < e1) {
        const float2* p0 = (const float2*)(hp + (size_t)csr[e] * 160);
        #pragma unroll
        for (int r = 0; r < 3; r++) {
            int idx = lane + 32 * r;
            if (idx < 78) {
                float2 v0 = p0[idx];
                acc[r].x += v0.x;
                acc[r].y += v0.y;
            }
        }
    }
    float din = dinv[n];
    float2* po = (float2*)(out + (size_t)n * 160);
    #pragma unroll
    for (int r = 0; r < 3; r++) {
        int idx = lane + 32 * r;
        if (idx < 78) po[idx] = make_float2(din * acc[r].x, din * acc[r].y);
    }
}

// -------- global max pool --------
__global__ void k_pool(const float* __restrict__ h,
                       const int* __restrict__ bat1, const int* __restrict__ bat2,
                       float* __restrict__ pool) {
    const int CH = 32;
    const int NCH = N2 / CH;
    int idx = blockIdx.x * blockDim.x + threadIdx.x;
    if (idx >= NCH * 312) return;
    int f = idx % 312;
    int c = idx / 312;
    int n0 = c * CH;
    int n1 = n0 + CH;
    int curb = (n0 < NN) ? bat1[n0] : GG + bat2[n0 - NN];
    float m = 0.f;
    for (int n = n0; n < n1; n++) {
        int b = (n < NN) ? bat1[n] : GG + bat2[n - NN];
        if (b != curb) {
            atomicMax((int*)&pool[curb * 312 + f], __float_as_int(m));
            curb = b;
            m = 0.f;
        }
        m = fmaxf(m, h[(size_t)n * 312 + f]);
    }
    atomicMax((int*)&pool[curb * 312 + f], __float_as_int(m));
}

// -------- scatter branch-MLP output [2G,128] -> xc[G,512] --------
__global__ void k_scatter(const float* __restrict__ t, float* __restrict__ xc) {
    int i = blockIdx.x * blockDim.x + threadIdx.x;
    if (i >= 2 * GG * 128) return;
    int r = i >> 7, j = i & 127;
    int br = r >> 8;
    int g = r & 255;
    xc[g * 512 + br * 128 + j] = t[i];
}

// -------- L2 row normalize --------
__global__ void k_norm(const float* __restrict__ cell, float* __restrict__ out) {
    int g = blockIdx.x;
    __shared__ float s[256];
    float ss = 0.f;
    for (int j = threadIdx.x; j < 954; j += 256) {
        float v = cell[g * 954 + j];
        ss += v * v;
    }
    s[threadIdx.x] = ss;
    __syncthreads();
    for (int o = 128; o > 0; o >>= 1) {
        if (threadIdx.x < o) s[threadIdx.x] += s[threadIdx.x + o];
        __syncthreads();
    }
    float inv = 1.f / fmaxf(sqrtf(s[0]), 1e-12f);
    for (int j = threadIdx.x; j < 954; j += 256)
        out[g * 954 + j] = cell[g * 954 + j] * inv;
}

// -------- trailing zero kernel: reset work + pool for the next call --------
__global__ void k_zero(int* __restrict__ work, float* __restrict__ pool) {
    int i = blockIdx.x * blockDim.x + threadIdx.x;
    if (i < 2 * N2) work[i] = 0;
    if (i < 2 * GG * 312) pool[i] = 0.f;
}

// ======== tensor-core node GEMM: bf16x3 split on mma.m16n8k16 ========
// C[M,N] = A[M,Kp](lda) @ B[Kr,N] + bias, relu, optional dinv row prescale.
// hi/lo bf16 planes are built in smem at load time (split cost out of inner loop).
// Block 128x64, BK=16 double-buffered, 8 warps of 32x32 (2x4 m16n8 tiles, 3 mma each).
template <bool RELU, bool PRESCALE>
__global__ __launch_bounds__(256)
void k_tgemm(const float* __restrict__ A, int lda,
             const float* __restrict__ B,
             const float* __restrict__ bias,
             const float* __restrict__ dinv,
             float* __restrict__ C, int ldc,
             int M, int N, int Kp, int Kr) {
    const int BM = 128, BN = 64;
    __shared__ uint32_t Ah[2][8][BM + 8], Al[2][8][BM + 8];   // [kpair][m], bf16x2(k,k+1)
    __shared__ uint32_t Bh[2][8][BN + 8], Bl[2][8][BN + 8];   // [kpair][n]
    int tid = threadIdx.x;
    int lane = tid & 31, wid = tid >> 5;
    int gid = lane >> 2, tq = lane & 3;
    int wm = (wid & 3) * 32, wn = (wid >> 2) * 32;
    int m0 = blockIdx.y * BM, n0 = blockIdx.x * BN;

    int arow = tid & 127;
    int akp = (tid >> 7) * 4;            // kpair base: 0 or 4
    const float* Ar = A + (size_t)(m0 + arow) * lda;
    int bn = tid & 63;
    int bkp = tid >> 6;                  // 0..3 (+4 for second slot)

    float acc[2][4][4];
    #pragma unroll
    for (int i = 0; i < 2; i++)
        #pragma unroll
        for (int j = 0; j < 4; j++)
            #pragma unroll
            for (int r = 0; r < 4; r++) acc[i][j][r] = 0.f;

    int ksteps = Kp / 16;

    // prologue: tile 0 -> buffer 0 (split to bf16 hi/lo at store)
    {
        float4 a0 = *(const float4*)(Ar + akp * 2);
        float4 a1 = *(const float4*)(Ar + akp * 2 + 4);
        bsplit2(a0.x, a0.y, Ah[0][akp + 0][arow], Al[0][akp + 0][arow]);
        bsplit2(a0.z, a0.w, Ah[0][akp + 1][arow], Al[0][akp + 1][arow]);
        bsplit2(a1.x, a1.y, Ah[0][akp + 2][arow], Al[0][akp + 2][arow]);
        bsplit2(a1.z, a1.w, Ah[0][akp + 3][arow], Al[0][akp + 3][arow]);
        #pragma unroll
        for (int h = 0; h < 2; h++) {
            int kp = bkp + 4 * h;
            int k = 2 * kp;
            int nn = n0 + bn;
            float f0 = (k < Kr && nn < N) ? B[(size_t)k * N + nn] : 0.f;
            float f1 = (k + 1 < Kr && nn < N) ? B[(size_t)(k + 1) * N + nn] : 0.f;
            bsplit2(f0, f1, Bh[0][kp][bn], Bl[0][kp][bn]);
        }
    }
    __syncthreads();

    for (int t = 0; t < ksteps; t++) {
        int cur = t & 1;
        bool more = (t + 1 < ksteps);
        float4 pa0, pa1;
        float pb[2][2];
        if (more) {
            int k0 = (t + 1) * 16;
            pa0 = *(const float4*)(Ar + k0 + akp * 2);
            pa1 = *(const float4*)(Ar + k0 + akp * 2 + 4);
            #pragma unroll
            for (int h = 0; h < 2; h++) {
                int k = k0 + 2 * (bkp + 4 * h);
                int nn = n0 + bn;
                pb[h][0] = (k < Kr && nn < N) ? B[(size_t)k * N + nn] : 0.f;
                pb[h][1] = (k + 1 < Kr && nn < N) ? B[(size_t)(k + 1) * N + nn] : 0.f;
            }
        }

        // fragments
        uint32_t ah[2][4], al[2][4], bh[4][2], bl[4][2];
        #pragma unroll
        for (int mi = 0; mi < 2; mi++) {
            int r = wm + mi * 16 + gid;
            ah[mi][0] = Ah[cur][tq][r];     al[mi][0] = Al[cur][tq][r];
            ah[mi][1] = Ah[cur][tq][r + 8]; al[mi][1] = Al[cur][tq][r + 8];
            ah[mi][2] = Ah[cur][tq + 4][r]; al[mi][2] = Al[cur][tq + 4][r];
            ah[mi][3] = Ah[cur][tq + 4][r + 8]; al[mi][3] = Al[cur][tq + 4][r + 8];
        }
        #pragma unroll
        for (int ni = 0; ni < 4; ni++) {
            int c = wn + ni * 8 + gid;
            bh[ni][0] = Bh[cur][tq][c];     bl[ni][0] = Bl[cur][tq][c];
            bh[ni][1] = Bh[cur][tq + 4][c]; bl[ni][1] = Bl[cur][tq + 4][c];
        }
        #pragma unroll
        for (int mi = 0; mi < 2; mi++)
            #pragma unroll
            for (int ni = 0; ni < 4; ni++) {
                mma16(acc[mi][ni], ah[mi], bh[ni]);
                mma16(acc[mi][ni], al[mi], bh[ni]);
                mma16(acc[mi][ni], ah[mi], bl[ni]);
            }

        if (more) {
            int nxt = cur ^ 1;
            bsplit2(pa0.x, pa0.y, Ah[nxt][akp + 0][arow], Al[nxt][akp + 0][arow]);
            bsplit2(pa0.z, pa0.w, Ah[nxt][akp + 1][arow], Al[nxt][akp + 1][arow]);
            bsplit2(pa1.x, pa1.y, Ah[nxt][akp + 2][arow], Al[nxt][akp + 2][arow]);
            bsplit2(pa1.z, pa1.w, Ah[nxt][akp + 3][arow], Al[nxt][akp + 3][arow]);
            #pragma unroll
            for (int h = 0; h < 2; h++) {
                int kp = bkp + 4 * h;
                bsplit2(pb[h][0], pb[h][1], Bh[nxt][kp][bn], Bl[nxt][kp][bn]);
            }
            __syncthreads();
        }
    }

    // epilogue: rows gid / gid+8, col pairs 2*tq, 2*tq+1 (N always even here)
    #pragma unroll
    for (int mi = 0; mi < 2; mi++) {
        int r0 = m0 + wm + mi * 16 + gid;
        int r1 = r0 + 8;
        float d0 = 1.f, d1 = 1.f;
        if (PRESCALE) {
            if (r0 < M) d0 = dinv[r0];
            if (r1 < M) d1 = dinv[r1];
        }
        #pragma unroll
        for (int ni = 0; ni < 4; ni++) {
            int cc = n0 + wn + ni * 8 + 2 * tq;
            if (cc >= N) continue;
            float b0 = bias[cc], b1 = bias[cc + 1];
            float* a = acc[mi][ni];
            float v00 = a[0] + b0, v01 = a[1] + b1;
            float v10 = a[2] + b0, v11 = a[3] + b1;
            if (RELU) {
                v00 = fmaxf(v00, 0.f); v01 = fmaxf(v01, 0.f);
                v10 = fmaxf(v10, 0.f); v11 = fmaxf(v11, 0.f);
            }
            if (PRESCALE) { v00 *= d0; v01 *= d0; v10 *= d1; v11 *= d1; }
            if (r0 < M) *(float2*)&C[(size_t)r0 * ldc + cc] = make_float2(v00, v01);
            if (r1 < M) *(float2*)&C[(size_t)r1 * ldc + cc] = make_float2(v10, v11);
        }
    }
}

static void gemm_node(const float* A, int lda, const float* B, const float* bias,
                      const float* dinv, float* C, int ldc, int M, int N,
                      int Kp, int Kr, bool prescale) {
    dim3 grid((N + 63) / 64, (M + 127) / 128);
    if (prescale)
        k_tgemm<true, true><<<grid, 256>>>(A, lda, B, bias, dinv, C, ldc, M, N, Kp, Kr);
    else
        k_tgemm<true, false><<<grid, 256>>>(A, lda, B, bias, dinv, C, ldc, M, N, Kp, Kr);
}

// -------- small SGEMM (64x64, BK=16) with optional split-K --------
template <bool RELU, bool PARTIAL>
__global__ void k_sgemm64(const float* __restrict__ A, int lda,
                          const float* __restrict__ B,
                          const float* __restrict__ bias,
                          float* __restrict__ C, int ldc,
                          int M, int N, int K, int Kc) {
    const int BM = 64, BN = 64, BK = 16;
    __shared__ float As[BK][BM];
    __shared__ float Bs[BK][BN];
    int m0 = blockIdx.y * BM;
    int n0 = blockIdx.x * BN;
    int s  = blockIdx.z;
    int kbeg = PARTIAL ? s * Kc : 0;
    int kend = PARTIAL ? min(K, kbeg + Kc) : K;
    int tid = threadIdx.x;
    int tx = tid & 15, ty = tid >> 4;
    float acc[4][4] = {};
    for (int k0 = kbeg; k0 < kend; k0 += BK) {
        #pragma unroll
        for (int i = 0; i < 4; i++) {
            int l = tid + 256 * i;
            int r = l >> 4, c = l & 15;
            int mm = m0 + r, kk = k0 + c;
            As[c][r] = (mm < M && kk < kend) ? A[mm * lda + kk] : 0.f;
        }
        #pragma unroll
        for (int i = 0; i < 4; i++) {
            int l = tid + 256 * i;
            int r = l >> 6, c = l & 63;
            int kk = k0 + r, nn = n0 + c;
            Bs[r][c] = (kk < kend && nn < N) ? B[kk * N + nn] : 0.f;
        }
        __syncthreads();
        #pragma unroll
        for (int kk = 0; kk < BK; kk++) {
            float a[4], b[4];
            #pragma unroll
            for (int i = 0; i < 4; i++) a[i] = As[kk][ty * 4 + i];
            #pragma unroll
            for (int j = 0; j < 4; j++) b[j] = Bs[kk][tx * 4 + j];
            #pragma unroll
            for (int i = 0; i < 4; i++)
                #pragma unroll
                for (int j = 0; j < 4; j++) acc[i][j] += a[i] * b[j];
        }
        __syncthreads();
    }
    #pragma unroll
    for (int i = 0; i < 4; i++) {
        int mm = m0 + ty * 4 + i;
        if (mm >= M) continue;
        #pragma unroll
        for (int j = 0; j < 4; j++) {
            int nn = n0 + tx * 4 + j;
            if (nn >= N) continue;
            if (PARTIAL) {
                C[(size_t)s * M * N + mm * N + nn] = acc[i][j];
            } else {
                float v = acc[i][j] + bias[nn];
                if (RELU) v = fmaxf(v, 0.f);
                C[mm * ldc + nn] = v;
            }
        }
    }
}

template <bool RELU>
__global__ void k_reduce(const float* __restrict__ part, int S,
                         const float* __restrict__ bias,
                         float* __restrict__ C, int ldc, int M, int N) {
    int i = blockIdx.x * blockDim.x + threadIdx.x;
    if (i >= M * N) return;
    int m = i / N, n = i % N;
    float v = 0.f;
    for (int s = 0; s < S; s++) v += part[(size_t)s * M * N + i];
    v += bias[n];
    if (RELU) v = fmaxf(v, 0.f);
    C[m * ldc + n] = v;
}

static void sgemm_split(const float* A, int lda, const float* B, const float* bias,
                        float* C, int ldc, int M, int N, int K, int S, bool relu,
                        float* part) {
    int Kc = (K + S - 1) / S;
    dim3 grid((N + 63) / 64, (M + 63) / 64, S);
    k_sgemm64<false, true><<<grid, 256>>>(A, lda, B, nullptr, part, 0, M, N, K, Kc);
    int tot = M * N;
    if (relu) k_reduce<true><<<(tot + 255) / 256, 256>>>(part, S, bias, C, ldc, M, N);
    else      k_reduce<false><<<(tot + 255) / 256, 256>>>(part, S, bias, C, ldc, M, N);
}

static void sgemm_small(const float* A, int lda, const float* B, const float* bias,
                        float* C, int ldc, int M, int N, int K, bool relu) {
    dim3 grid((N + 63) / 64, (M + 63) / 64, 1);
    if (relu) k_sgemm64<true, false><<<grid, 256>>>(A, lda, B, bias, C, ldc, M, N, K, K);
    else      k_sgemm64<false, false><<<grid, 256>>>(A, lda, B, bias, C, ldc, M, N, K, K);
}

extern "C" void kernel_launch(void* const* d_in, const int* in_sizes, int n_in,
                              void* d_out, int out_size) {
    const float* x1   = (const float*)d_in[0];
    const int*   ei1  = (const int*)d_in[1];
    const int*   bat1 = (const int*)d_in[2];
    const float* x2   = (const float*)d_in[3];
    const int*   ei2  = (const int*)d_in[4];
    const int*   bat2 = (const int*)d_in[5];
    const float* cell = (const float*)d_in[6];
    const float* Wc1 = (const float*)d_in[7];  const float* bc1 = (const float*)d_in[8];
    const float* Wc2 = (const float*)d_in[9];  const float* bc2 = (const float*)d_in[10];
    const float* Wc3 = (const float*)d_in[11]; const float* bc3 = (const float*)d_in[12];
    const float* Wg1 = (const float*)d_in[13]; const float* bg1 = (const float*)d_in[14];
    const float* Wg2 = (const float*)d_in[15]; const float* bg2 = (const float*)d_in[16];
    const float* Wr1 = (const float*)d_in[17]; const float* br1 = (const float*)d_in[18];
    const float* Wr2 = (const float*)d_in[19]; const float* br2 = (const float*)d_in[20];
    const float* Wr3 = (const float*)d_in[21]; const float* br3 = (const float*)d_in[22];
    const float* Wf1 = (const float*)d_in[23]; const float* bf1 = (const float*)d_in[24];
    const float* Wf2 = (const float*)d_in[25]; const float* bf2 = (const float*)d_in[26];
    const float* Wf3 = (const float*)d_in[27]; const float* bf3 = (const float*)d_in[28];
    const float* Wo  = (const float*)d_in[29]; const float* bo  = (const float*)d_in[30];
    float* out = (float*)d_out;

    float *bufA, *bufP, *bufQ, *bufB, *dinv, *pool, *xc, *t0, *t1, *part;
    int *work, *offs, *csr;
    cudaGetSymbolAddress((void**)&bufA, g_bufA);
    cudaGetSymbolAddress((void**)&bufP, g_bufP);
    cudaGetSymbolAddress((void**)&bufQ, g_bufQ);
    cudaGetSymbolAddress((void**)&bufB, g_bufB);
    cudaGetSymbolAddress((void**)&work, g_work);
    cudaGetSymbolAddress((void**)&offs, g_offs);
    cudaGetSymbolAddress((void**)&csr,  g_csr);
    cudaGetSymbolAddress((void**)&dinv, g_dinv);
    cudaGetSymbolAddress((void**)&pool, g_pool);
    cudaGetSymbolAddress((void**)&xc,   g_xc);
    cudaGetSymbolAddress((void**)&t0,   g_t0);
    cudaGetSymbolAddress((void**)&t1,   g_t1);
    cudaGetSymbolAddress((void**)&part, g_part);
    int* cnt  = work;
    int* fill = work + N2;

    const int EB2 = (E2 + 255) / 256;
    const int AGGB = (N2 * 32 + 255) / 256;

    // ---- launch 1: cell normalize (independent; also aligns profiling slots)
    k_norm<<<GG, 256>>>(cell, t0);

    // ---- CSR build (work/cnt/fill arrive zeroed: statics at first call, k_zero after)
    k_count2<<<EB2, 256>>>(ei1, ei2, cnt);
    k_scan_dinv<<<1, 1024>>>(cnt, offs, dinv);
    k_fill2<<<EB2, 256>>>(ei1, ei2, offs, fill, csr);

    // ---- GCN layers (M = 40000), bf16x3 tensor GEMMs. slot 6 = gemm1.
    k_agg_l1<<<AGGB, 256>>>(x1, x2, offs, csr, dinv, bufA);
    gemm_node(bufA, 80, Wc1, bc1, dinv, bufP, 80, N2, 78, 80, 78, true);
    k_agg_pre<<<AGGB, 256>>>(bufP, offs, csr, dinv, bufA);
    gemm_node(bufA, 80, Wc2, bc2, dinv, bufQ, 160, N2, 156, 80, 78, true);
    k_agg_pre2<<<AGGB, 256>>>(bufQ, offs, csr, dinv, bufA);
    gemm_node(bufA, 160, Wc3, bc3, dinv, bufB, 312, N2, 312, 160, 156, false);

    // ---- global max pool -> [2G, 312] (pool arrives zeroed)
    int pthreads = (N2 / 32) * 312;
    k_pool<<<(pthreads + 255) / 256, 256>>>(bufB, bat1, bat2, pool);

    // ---- branch MLP batched (M = 512)
    sgemm_split(pool, 312, Wg1, bg1, t0 + GG * 2048, 156, 2 * GG, 156, 312, 4, true, part);
    sgemm_split(t0 + GG * 2048, 156, Wg2, bg2, t1 + GG * 2048, 128, 2 * GG, 128, 156, 2, false, part);
    k_scatter<<<(2 * GG * 128 + 255) / 256, 256>>>(t1 + GG * 2048, xc);

    // ---- cell reduction MLP -> xc cols [256..512)  (t0[0:G*954] holds normalized cell)
    sgemm_split(t0, 954, Wr1, br1, t1, 2048, GG, 2048, 954, 2, true, part);
    sgemm_split(t1, 2048, Wr2, br2, t0, 512, GG, 512, 2048, 8, true, part);
    sgemm_split(t0, 512, Wr3, br3, xc + 256, 512, GG, 256, 512, 4, true, part);

    // ---- head MLP
    sgemm_split(xc, 512, Wf1, bf1, t0, 1024, GG, 1024, 512, 2, true, part);
    sgemm_split(t0, 1024, Wf2, bf2, t1, 512, GG, 512, 1024, 4, true, part);
    sgemm_split(t1, 512, Wf3, bf3, t0, 128, GG, 128, 512, 4, true, part);
    sgemm_small(t0, 128, Wo, bo, out, 2, GG, 2, 128, false);

    // ---- reset work + pool for the next invocation (deterministic per-call state)
    k_zero<<<(2 * GG * 312 + 255) / 256, 256>>>(work, pool);
}

// round 7
// speedup vs baseline: 2.2044x; 1.0325x over previous
#include <cuda_runtime.h>
#include <cuda_bf16.h>
#include <cstdint>

#define NN 20000
#define EE 320000
#define GG 256
#define N2 (2 * NN)
#define E2 (2 * EE)

// -------- scratch (static device globals; zero-init, no runtime allocation) --------
__device__ float g_bufA[(N2 + 256) * 160];
__device__ float g_bufP[(N2 + 256) * 80];
__device__ float g_bufQ[(N2 + 256) * 160];
__device__ float g_bufB[(N2 + 256) * 312];
__device__ int   g_work[2 * N2];
__device__ int   g_offs[N2 + 1];
__device__ int   g_csr[E2];
__device__ float g_dinv[N2];
__device__ float g_pool[2 * GG * 320];       // ld 320 (16-mult); re-zeroed each call
__device__ float g_xc[GG * 512];
__device__ float g_t0[2 * GG * 2048];
__device__ float g_t1[2 * GG * 2048];
__device__ float g_part[8 * GG * 1024];

// -------- bf16 split helpers --------
__device__ __forceinline__ void bsplit2(float x, float y, uint32_t& hi, uint32_t& lo) {
    __nv_bfloat162 h = __floats2bfloat162_rn(x, y);
    float rx = x - __bfloat162float(h.x);
    float ry = y - __bfloat162float(h.y);
    __nv_bfloat162 l = __floats2bfloat162_rn(rx, ry);
    hi = *reinterpret_cast<uint32_t*>(&h);
    lo = *reinterpret_cast<uint32_t*>(&l);
}
__device__ __forceinline__ void mma16(float* c, const uint32_t* a, const uint32_t* b) {
    asm("mma.sync.aligned.m16n8k16.row.col.f32.bf16.bf16.f32 "
        "{%0,%1,%2,%3}, {%4,%5,%6,%7}, {%8,%9}, {%0,%1,%2,%3};"
        : "+f"(c[0]), "+f"(c[1]), "+f"(c[2]), "+f"(c[3])
        : "r"(a[0]), "r"(a[1]), "r"(a[2]), "r"(a[3]), "r"(b[0]), "r"(b[1]));
}

// -------- CSR build --------
__global__ void k_count2(const int* __restrict__ ei1, const int* __restrict__ ei2,
                         int* __restrict__ cnt) {
    int e = blockIdx.x * blockDim.x + threadIdx.x;
    if (e < EE) atomicAdd(&cnt[ei1[EE + e]], 1);
    else if (e < E2) atomicAdd(&cnt[ei2[EE + (e - EE)] + NN], 1);
}

__global__ void k_scan_dinv(const int* __restrict__ cnt, int* __restrict__ offs,
                            float* __restrict__ dinv) {
    const int T = 1024;
    const int IPT = (N2 + T - 1) / T;
    __shared__ int s[T];
    int tid = threadIdx.x;
    int base = tid * IPT;
    int local = 0;
    #pragma unroll
    for (int i = 0; i < IPT; i++) {
        int idx = base + i;
        if (idx < N2) {
            int c = cnt[idx];
            local += c;
            dinv[idx] = rsqrtf((float)(c + 1));
        }
    }
    s[tid] = local;
    __syncthreads();
    for (int off = 1; off < T; off <<= 1) {
        int v = 0;
        if (tid >= off) v = s[tid - off];
        __syncthreads();
        if (tid >= off) s[tid] += v;
        __syncthreads();
    }
    int run = (tid == 0) ? 0 : s[tid - 1];
    #pragma unroll
    for (int i = 0; i < IPT; i++) {
        int idx = base + i;
        if (idx < N2) { offs[idx] = run; run += cnt[idx]; }
    }
    if (tid == 0) offs[N2] = s[T - 1];
}

__global__ void k_fill2(const int* __restrict__ ei1, const int* __restrict__ ei2,
                        const int* __restrict__ offs, int* __restrict__ fill,
                        int* __restrict__ csr) {
    int e = blockIdx.x * blockDim.x + threadIdx.x;
    int s, d;
    if (e < EE) { s = ei1[e]; d = ei1[EE + e]; }
    else if (e < E2) { s = ei2[e - EE] + NN; d = ei2[EE + (e - EE)] + NN; }
    else return;
    int p = atomicAdd(&fill[d], 1);
    csr[offs[d] + p] = s;
}

// -------- aggregations --------
__global__ void k_agg_l1(const float* __restrict__ h0, const float* __restrict__ h1,
                         const int* __restrict__ offs, const int* __restrict__ csr,
                         const float* __restrict__ dinv, float* __restrict__ out) {
    int warp = (blockIdx.x * blockDim.x + threadIdx.x) >> 5;
    int lane = threadIdx.x & 31;
    if (warp >= N2) return;
    int n = warp;
    const float* hn = (n < NN) ? h0 + (size_t)n * 78 : h1 + (size_t)(n - NN) * 78;
    float din = dinv[n];
    float acc[3];
    #pragma unroll
    for (int r = 0; r < 3; r++) {
        int f = lane + 32 * r;
        acc[r] = (f < 78) ? din * hn[f] : 0.f;
    }
    int e0 = offs[n], e1 = offs[n + 1];
    for (int e = e0; e < e1; e++) {
        int s = csr[e];
        const float* hs = (s < NN) ? h0 + (size_t)s * 78 : h1 + (size_t)(s - NN) * 78;
        float ds = dinv[s];
        #pragma unroll
        for (int r = 0; r < 3; r++) {
            int f = lane + 32 * r;
            if (f < 78) acc[r] += ds * hs[f];
        }
    }
    #pragma unroll
    for (int r = 0; r < 3; r++) {
        int f = lane + 32 * r;
        if (f < 78) out[(size_t)n * 80 + f] = din * acc[r];
    }
}

__global__ void k_agg_pre(const float* __restrict__ hp, const int* __restrict__ offs,
                          const int* __restrict__ csr, const float* __restrict__ dinv,
                          float* __restrict__ out) {
    int warp = (blockIdx.x * blockDim.x + threadIdx.x) >> 5;
    int lane = threadIdx.x & 31;
    if (warp >= N2) return;
    int n = warp;
    float acc[3];
    #pragma unroll
    for (int r = 0; r < 3; r++) {
        int f = lane + 32 * r;
        acc[r] = (f < 78) ? hp[(size_t)n * 80 + f] : 0.f;
    }
    int e0 = offs[n], e1 = offs[n + 1];
    int e = e0;
    for (; e + 2 <= e1; e += 2) {
        int s0 = csr[e], s1 = csr[e + 1];
        const float* p0 = hp + (size_t)s0 * 80;
        const float* p1 = hp + (size_t)s1 * 80;
        #pragma unroll
        for (int r = 0; r < 3; r++) {
            int f = lane + 32 * r;
            if (f < 78) acc[r] += p0[f] + p1[f];
        }
    }
    if (e < e1) {
        const float* p0 = hp + (size_t)csr[e] * 80;
        #pragma unroll
        for (int r = 0; r < 3; r++) {
            int f = lane + 32 * r;
            if (f < 78) acc[r] += p0[f];
        }
    }
    float din = dinv[n];
    #pragma unroll
    for (int r = 0; r < 3; r++) {
        int f = lane + 32 * r;
        if (f < 78) out[(size_t)n * 80 + f] = din * acc[r];
    }
}

__global__ void k_agg_pre2(const float* __restrict__ hp, const int* __restrict__ offs,
                           const int* __restrict__ csr, const float* __restrict__ dinv,
                           float* __restrict__ out) {
    int warp = (blockIdx.x * blockDim.x + threadIdx.x) >> 5;
    int lane = threadIdx.x & 31;
    if (warp >= N2) return;
    int n = warp;
    const float2* pn = (const float2*)(hp + (size_t)n * 160);
    float2 acc[3];
    #pragma unroll
    for (int r = 0; r < 3; r++) {
        int idx = lane + 32 * r;
        acc[r] = (idx < 78) ? pn[idx] : make_float2(0.f, 0.f);
    }
    int e0 = offs[n], e1 = offs[n + 1];
    int e = e0;
    for (; e + 2 <= e1; e += 2) {
        int s0 = csr[e], s1 = csr[e + 1];
        const float2* p0 = (const float2*)(hp + (size_t)s0 * 160);
        const float2* p1 = (const float2*)(hp + (size_t)s1 * 160);
        #pragma unroll
        for (int r = 0; r < 3; r++) {
            int idx = lane + 32 * r;
            if (idx < 78) {
                float2 v0 = p0[idx], v1 = p1[idx];
                acc[r].x += v0.x + v1.x;
                acc[r].y += v0.y + v1.y;
            }
        }
    }
    if (e < e1) {
        const float2* p0 = (const float2*)(hp + (size_t)csr[e] * 160);
        #pragma unroll
        for (int r = 0; r < 3; r++) {
            int idx = lane + 32 * r;
            if (idx < 78) {
                float2 v0 = p0[idx];
                acc[r].x += v0.x;
                acc[r].y += v0.y;
            }
        }
    }
    float din = dinv[n];
    float2* po = (float2*)(out + (size_t)n * 160);
    #pragma unroll
    for (int r = 0; r < 3; r++) {
        int idx = lane + 32 * r;
        if (idx < 78) po[idx] = make_float2(din * acc[r].x, din * acc[r].y);
    }
}

// -------- global max pool (pool ld 320) --------
__global__ void k_pool(const float* __restrict__ h,
                       const int* __restrict__ bat1, const int* __restrict__ bat2,
                       float* __restrict__ pool) {
    const int CH = 32;
    const int NCH = N2 / CH;
    int idx = blockIdx.x * blockDim.x + threadIdx.x;
    if (idx >= NCH * 312) return;
    int f = idx % 312;
    int c = idx / 312;
    int n0 = c * CH;
    int n1 = n0 + CH;
    int curb = (n0 < NN) ? bat1[n0] : GG + bat2[n0 - NN];
    float m = 0.f;
    for (int n = n0; n < n1; n++) {
        int b = (n < NN) ? bat1[n] : GG + bat2[n - NN];
        if (b != curb) {
            atomicMax((int*)&pool[curb * 320 + f], __float_as_int(m));
            curb = b;
            m = 0.f;
        }
        m = fmaxf(m, h[(size_t)n * 312 + f]);
    }
    atomicMax((int*)&pool[curb * 320 + f], __float_as_int(m));
}

// -------- scatter branch-MLP output [2G,128] -> xc[G,512] --------
__global__ void k_scatter(const float* __restrict__ t, float* __restrict__ xc) {
    int i = blockIdx.x * blockDim.x + threadIdx.x;
    if (i >= 2 * GG * 128) return;
    int r = i >> 7, j = i & 127;
    int br = r >> 8;
    int g = r & 255;
    xc[g * 512 + br * 128 + j] = t[i];
}

// -------- L2 row normalize -> ld 960 (zero pads) --------
__global__ void k_norm(const float* __restrict__ cell, float* __restrict__ out) {
    int g = blockIdx.x;
    __shared__ float s[256];
    float ss = 0.f;
    for (int j = threadIdx.x; j < 954; j += 256) {
        float v = cell[g * 954 + j];
        ss += v * v;
    }
    s[threadIdx.x] = ss;
    __syncthreads();
    for (int o = 128; o > 0; o >>= 1) {
        if (threadIdx.x < o) s[threadIdx.x] += s[threadIdx.x + o];
        __syncthreads();
    }
    float inv = 1.f / fmaxf(sqrtf(s[0]), 1e-12f);
    for (int j = threadIdx.x; j < 960; j += 256)
        out[g * 960 + j] = (j < 954) ? cell[g * 954 + j] * inv : 0.f;
}

// -------- trailing zero kernel --------
__global__ void k_zero(int* __restrict__ work, float* __restrict__ pool) {
    int i = blockIdx.x * blockDim.x + threadIdx.x;
    if (i < 2 * N2) work[i] = 0;
    if (i < 2 * GG * 320) pool[i] = 0.f;
}

// ======== tensor-core GEMM: bf16x3 split on mma.m16n8k16 ========
// Block 128x64, BK=16 double-buffered, 8 warps of 32x32.
// SPLITK: blockIdx.z k-slice [z*Kc, min(Kp,(z+1)*Kc)), writes fp32 partials (no bias).
template <bool RELU, bool PRESCALE, bool SPLITK>
__global__ __launch_bounds__(256)
void k_tgemm(const float* __restrict__ A, int lda,
             const float* __restrict__ B,
             const float* __restrict__ bias,
             const float* __restrict__ dinv,
             float* __restrict__ C, int ldc,
             int M, int N, int Kp, int Kr, int Kc) {
    const int BM = 128, BN = 64;
    __shared__ uint32_t Ah[2][8][BM + 8], Al[2][8][BM + 8];
    __shared__ uint32_t Bh[2][8][BN + 8], Bl[2][8][BN + 8];
    int tid = threadIdx.x;
    int lane = tid & 31, wid = tid >> 5;
    int gid = lane >> 2, tq = lane & 3;
    int wm = (wid & 3) * 32, wn = (wid >> 2) * 32;
    int m0 = blockIdx.y * BM, n0 = blockIdx.x * BN;
    int kbeg = SPLITK ? blockIdx.z * Kc : 0;
    int kend = SPLITK ? min(Kp, kbeg + Kc) : Kp;

    int arow = tid & 127;
    int akp = (tid >> 7) * 4;
    const float* Ar = A + (size_t)(m0 + arow) * lda + kbeg;
    int bn = tid & 63;
    int bkp = tid >> 6;

    float acc[2][4][4];
    #pragma unroll
    for (int i = 0; i < 2; i++)
        #pragma unroll
        for (int j = 0; j < 4; j++)
            #pragma unroll
            for (int r = 0; r < 4; r++) acc[i][j][r] = 0.f;

    int ksteps = (kend - kbeg) / 16;

    {
        float4 a0 = *(const float4*)(Ar + akp * 2);
        float4 a1 = *(const float4*)(Ar + akp * 2 + 4);
        bsplit2(a0.x, a0.y, Ah[0][akp + 0][arow], Al[0][akp + 0][arow]);
        bsplit2(a0.z, a0.w, Ah[0][akp + 1][arow], Al[0][akp + 1][arow]);
        bsplit2(a1.x, a1.y, Ah[0][akp + 2][arow], Al[0][akp + 2][arow]);
        bsplit2(a1.z, a1.w, Ah[0][akp + 3][arow], Al[0][akp + 3][arow]);
        #pragma unroll
        for (int h = 0; h < 2; h++) {
            int kp = bkp + 4 * h;
            int k = kbeg + 2 * kp;
            int nn = n0 + bn;
            float f0 = (k < Kr && nn < N) ? B[(size_t)k * N + nn] : 0.f;
            float f1 = (k + 1 < Kr && nn < N) ? B[(size_t)(k + 1) * N + nn] : 0.f;
            bsplit2(f0, f1, Bh[0][kp][bn], Bl[0][kp][bn]);
        }
    }
    __syncthreads();

    for (int t = 0; t < ksteps; t++) {
        int cur = t & 1;
        bool more = (t + 1 < ksteps);
        float4 pa0, pa1;
        float pb[2][2];
        if (more) {
            int k0 = (t + 1) * 16;
            pa0 = *(const float4*)(Ar + k0 + akp * 2);
            pa1 = *(const float4*)(Ar + k0 + akp * 2 + 4);
            #pragma unroll
            for (int h = 0; h < 2; h++) {
                int k = kbeg + k0 + 2 * (bkp + 4 * h);
                int nn = n0 + bn;
                pb[h][0] = (k < Kr && nn < N) ? B[(size_t)k * N + nn] : 0.f;
                pb[h][1] = (k + 1 < Kr && nn < N) ? B[(size_t)(k + 1) * N + nn] : 0.f;
            }
        }

        uint32_t ah[2][4], al[2][4], bh[4][2], bl[4][2];
        #pragma unroll
        for (int mi = 0; mi < 2; mi++) {
            int r = wm + mi * 16 + gid;
            ah[mi][0] = Ah[cur][tq][r];     al[mi][0] = Al[cur][tq][r];
            ah[mi][1] = Ah[cur][tq][r + 8]; al[mi][1] = Al[cur][tq][r + 8];
            ah[mi][2] = Ah[cur][tq + 4][r]; al[mi][2] = Al[cur][tq + 4][r];
            ah[mi][3] = Ah[cur][tq + 4][r + 8]; al[mi][3] = Al[cur][tq + 4][r + 8];
        }
        #pragma unroll
        for (int ni = 0; ni < 4; ni++) {
            int c = wn + ni * 8 + gid;
            bh[ni][0] = Bh[cur][tq][c];     bl[ni][0] = Bl[cur][tq][c];
            bh[ni][1] = Bh[cur][tq + 4][c]; bl[ni][1] = Bl[cur][tq + 4][c];
        }
        #pragma unroll
        for (int mi = 0; mi < 2; mi++)
            #pragma unroll
            for (int ni = 0; ni < 4; ni++) {
                mma16(acc[mi][ni], ah[mi], bh[ni]);
                mma16(acc[mi][ni], al[mi], bh[ni]);
                mma16(acc[mi][ni], ah[mi], bl[ni]);
            }

        if (more) {
            int nxt = cur ^ 1;
            bsplit2(pa0.x, pa0.y, Ah[nxt][akp + 0][arow], Al[nxt][akp + 0][arow]);
            bsplit2(pa0.z, pa0.w, Ah[nxt][akp + 1][arow], Al[nxt][akp + 1][arow]);
            bsplit2(pa1.x, pa1.y, Ah[nxt][akp + 2][arow], Al[nxt][akp + 2][arow]);
            bsplit2(pa1.z, pa1.w, Ah[nxt][akp + 3][arow], Al[nxt][akp + 3][arow]);
            #pragma unroll
            for (int h = 0; h < 2; h++) {
                int kp = bkp + 4 * h;
                bsplit2(pb[h][0], pb[h][1], Bh[nxt][kp][bn], Bl[nxt][kp][bn]);
            }
            __syncthreads();
        }
    }

    #pragma unroll
    for (int mi = 0; mi < 2; mi++) {
        int r0 = m0 + wm + mi * 16 + gid;
        int r1 = r0 + 8;
        float d0 = 1.f, d1 = 1.f;
        if (PRESCALE) {
            if (r0 < M) d0 = dinv[r0];
            if (r1 < M) d1 = dinv[r1];
        }
        #pragma unroll
        for (int ni = 0; ni < 4; ni++) {
            int cc = n0 + wn + ni * 8 + 2 * tq;
            if (cc >= N) continue;
            float* a = acc[mi][ni];
            if (SPLITK) {
                size_t base = (size_t)blockIdx.z * M * N;
                if (r0 < M) *(float2*)&C[base + (size_t)r0 * N + cc] = make_float2(a[0], a[1]);
                if (r1 < M) *(float2*)&C[base + (size_t)r1 * N + cc] = make_float2(a[2], a[3]);
            } else {
                float b0 = bias[cc], b1 = bias[cc + 1];
                float v00 = a[0] + b0, v01 = a[1] + b1;
                float v10 = a[2] + b0, v11 = a[3] + b1;
                if (RELU) {
                    v00 = fmaxf(v00, 0.f); v01 = fmaxf(v01, 0.f);
                    v10 = fmaxf(v10, 0.f); v11 = fmaxf(v11, 0.f);
                }
                if (PRESCALE) { v00 *= d0; v01 *= d0; v10 *= d1; v11 *= d1; }
                if (r0 < M) *(float2*)&C[(size_t)r0 * ldc + cc] = make_float2(v00, v01);
                if (r1 < M) *(float2*)&C[(size_t)r1 * ldc + cc] = make_float2(v10, v11);
            }
        }
    }
}

template <bool RELU>
__global__ void k_reduce(const float* __restrict__ part, int S,
                         const float* __restrict__ bias,
                         float* __restrict__ C, int ldc, int M, int N) {
    int i = blockIdx.x * blockDim.x + threadIdx.x;
    if (i >= M * N) return;
    int m = i / N, n = i % N;
    float v = 0.f;
    for (int s = 0; s < S; s++) v += part[(size_t)s * M * N + i];
    v += bias[n];
    if (RELU) v = fmaxf(v, 0.f);
    C[m * ldc + n] = v;
}

static void gemm_node(const float* A, int lda, const float* B, const float* bias,
                      const float* dinv, float* C, int ldc, int M, int N,
                      int Kp, int Kr, bool prescale) {
    dim3 grid((N + 63) / 64, (M + 127) / 128);
    if (prescale)
        k_tgemm<true, true, false><<<grid, 256>>>(A, lda, B, bias, dinv, C, ldc, M, N, Kp, Kr, Kp);
    else
        k_tgemm<true, false, false><<<grid, 256>>>(A, lda, B, bias, dinv, C, ldc, M, N, Kp, Kr, Kp);
}

// tensor MLP GEMM with optional split-K (relu handled in epilogue or reduce)
static void tgemm(const float* A, int lda, const float* B, const float* bias,
                  float* C, int ldc, int M, int N, int Kp, int Kr,
                  int S, bool relu, float* part) {
    if (S <= 1) {
        dim3 grid((N + 63) / 64, (M + 127) / 128);
        if (relu)
            k_tgemm<true, false, false><<<grid, 256>>>(A, lda, B, bias, nullptr, C, ldc, M, N, Kp, Kr, Kp);
        else
            k_tgemm<false, false, false><<<grid, 256>>>(A, lda, B, bias, nullptr, C, ldc, M, N, Kp, Kr, Kp);
        return;
    }
    int Kc = ((Kp / S + 15) / 16) * 16;
    if (Kc < 16) Kc = 16;
    int Se = (Kp + Kc - 1) / Kc;
    dim3 grid((N + 63) / 64, (M + 127) / 128, Se);
    k_tgemm<false, false, true><<<grid, 256>>>(A, lda, B, nullptr, nullptr, part, 0, M, N, Kp, Kr, Kc);
    int tot = M * N;
    if (relu) k_reduce<true><<<(tot + 255) / 256, 256>>>(part, Se, bias, C, ldc, M, N);
    else      k_reduce<false><<<(tot + 255) / 256, 256>>>(part, Se, bias, C, ldc, M, N);
}

// -------- tiny scalar GEMM for the final 256x2x128 --------
__global__ void k_wo(const float* __restrict__ A, const float* __restrict__ B,
                     const float* __restrict__ bias, float* __restrict__ C) {
    // A: [256,128] ld128, B: [128,2], C: [256,2]
    int g = blockIdx.x * blockDim.x + threadIdx.x;
    if (g >= GG * 2) return;
    int m = g >> 1, n = g & 1;
    float v = 0.f;
    const float* a = A + m * 128;
    for (int k = 0; k < 128; k++) v += a[k] * B[k * 2 + n];
    C[g] = v + bias[n];
}

extern "C" void kernel_launch(void* const* d_in, const int* in_sizes, int n_in,
                              void* d_out, int out_size) {
    const float* x1   = (const float*)d_in[0];
    const int*   ei1  = (const int*)d_in[1];
    const int*   bat1 = (const int*)d_in[2];
    const float* x2   = (const float*)d_in[3];
    const int*   ei2  = (const int*)d_in[4];
    const int*   bat2 = (const int*)d_in[5];
    const float* cell = (const float*)d_in[6];
    const float* Wc1 = (const float*)d_in[7];  const float* bc1 = (const float*)d_in[8];
    const float* Wc2 = (const float*)d_in[9];  const float* bc2 = (const float*)d_in[10];
    const float* Wc3 = (const float*)d_in[11]; const float* bc3 = (const float*)d_in[12];
    const float* Wg1 = (const float*)d_in[13]; const float* bg1 = (const float*)d_in[14];
    const float* Wg2 = (const float*)d_in[15]; const float* bg2 = (const float*)d_in[16];
    const float* Wr1 = (const float*)d_in[17]; const float* br1 = (const float*)d_in[18];
    const float* Wr2 = (const float*)d_in[19]; const float* br2 = (const float*)d_in[20];
    const float* Wr3 = (const float*)d_in[21]; const float* br3 = (const float*)d_in[22];
    const float* Wf1 = (const float*)d_in[23]; const float* bf1 = (const float*)d_in[24];
    const float* Wf2 = (const float*)d_in[25]; const float* bf2 = (const float*)d_in[26];
    const float* Wf3 = (const float*)d_in[27]; const float* bf3 = (const float*)d_in[28];
    const float* Wo  = (const float*)d_in[29]; const float* bo  = (const float*)d_in[30];
    float* out = (float*)d_out;

    float *bufA, *bufP, *bufQ, *bufB, *dinv, *pool, *xc, *t0, *t1, *part;
    int *work, *offs, *csr;
    cudaGetSymbolAddress((void**)&bufA, g_bufA);
    cudaGetSymbolAddress((void**)&bufP, g_bufP);
    cudaGetSymbolAddress((void**)&bufQ, g_bufQ);
    cudaGetSymbolAddress((void**)&bufB, g_bufB);
    cudaGetSymbolAddress((void**)&work, g_work);
    cudaGetSymbolAddress((void**)&offs, g_offs);
    cudaGetSymbolAddress((void**)&csr,  g_csr);
    cudaGetSymbolAddress((void**)&dinv, g_dinv);
    cudaGetSymbolAddress((void**)&pool, g_pool);
    cudaGetSymbolAddress((void**)&xc,   g_xc);
    cudaGetSymbolAddress((void**)&t0,   g_t0);
    cudaGetSymbolAddress((void**)&t1,   g_t1);
    cudaGetSymbolAddress((void**)&part, g_part);
    int* cnt  = work;
    int* fill = work + N2;

    const int EB2 = (E2 + 255) / 256;
    const int AGGB = (N2 * 32 + 255) / 256;

    // ---- cell normalize (ld 960, zero-padded)
    k_norm<<<GG, 256>>>(cell, t0);

    // ---- CSR build (work arrives zeroed)
    k_count2<<<EB2, 256>>>(ei1, ei2, cnt);
    k_scan_dinv<<<1, 1024>>>(cnt, offs, dinv);
    k_fill2<<<EB2, 256>>>(ei1, ei2, offs, fill, csr);

    // ---- GCN layers (M = 40000), bf16x3 tensor GEMMs
    k_agg_l1<<<AGGB, 256>>>(x1, x2, offs, csr, dinv, bufA);
    gemm_node(bufA, 80, Wc1, bc1, dinv, bufP, 80, N2, 78, 80, 78, true);
    k_agg_pre<<<AGGB, 256>>>(bufP, offs, csr, dinv, bufA);
    gemm_node(bufA, 80, Wc2, bc2, dinv, bufQ, 160, N2, 156, 80, 78, true);
    k_agg_pre2<<<AGGB, 256>>>(bufQ, offs, csr, dinv, bufA);
    gemm_node(bufA, 160, Wc3, bc3, dinv, bufB, 312, N2, 312, 160, 156, false);

    // ---- global max pool -> [2G, 320] (zeroed; pads stay 0)
    int pthreads = (N2 / 32) * 312;
    k_pool<<<(pthreads + 255) / 256, 256>>>(bufB, bat1, bat2, pool);

    // ---- branch MLP batched (M = 512), tensor
    float* tb0 = t0 + GG * 2048;   // [512,160]
    float* tb1 = t1 + GG * 2048;   // [512,128]
    tgemm(pool, 320, Wg1, bg1, tb0, 160, 2 * GG, 156, 320, 312, 2, true, part);
    tgemm(tb0, 160, Wg2, bg2, tb1, 128, 2 * GG, 128, 160, 156, 2, false, part);
    k_scatter<<<(2 * GG * 128 + 255) / 256, 256>>>(tb1, xc);

    // ---- cell reduction MLP -> xc cols [256..512)
    tgemm(t0, 960, Wr1, br1, t1, 2048, GG, 2048, 960, 954, 2, true, part);
    tgemm(t1, 2048, Wr2, br2, t0, 512, GG, 512, 2048, 2048, 4, true, part);
    tgemm(t0, 512, Wr3, br3, xc + 256, 512, GG, 256, 512, 512, 4, true, part);

    // ---- head MLP
    tgemm(xc, 512, Wf1, bf1, t0, 1024, GG, 1024, 512, 512, 2, true, part);
    tgemm(t0, 1024, Wf2, bf2, t1, 512, GG, 512, 1024, 1024, 4, true, part);
    tgemm(t1, 512, Wf3, bf3, t0, 128, GG, 128, 512, 512, 4, true, part);
    k_wo<<<(GG * 2 + 255) / 256, 256>>>(t0, Wo, bo, out);

    // ---- reset work + pool
    k_zero<<<(2 * GG * 320 + 255) / 256, 256>>>(work, pool);
}